// round 6
// baseline (speedup 1.0000x reference)
#include <cuda_runtime.h>
#include <cuda_bf16.h>
#include <math.h>
#include <stdint.h>
#include <string.h>

#define B_ 32
#define S_ 64
#define T_ 16
#define U_ 1024
#define E_ 256
#define V_ 20200
#define G_ 3072          /* 3*U */
#define VP_ 20224        /* V padded to 64 */
#define NB_ 128          /* persistent grid blocks */
#define UGS 3080         /* encoder smem stride per ug (3*1024 + pad8) */
#define WGS 3848         /* decoder dWx smem stride per ug (3*1280 + pad8) */
#define QS_ 1032         /* decoder W2 smem stride per cq (1024 + pad8) */

// ---------------- device scratch ----------------
__device__ __align__(16) float d_gxall[S_*B_*G_];           // [s*32+b][3072]
__device__ __align__(16) float d_hbuf[2][B_*U_];            // encoder hidden ping-pong
__device__ __align__(16) float d_hdec[B_*U_];               // decoder hidden
__device__ __align__(16) float d_enc[B_*S_*U_];             // encoded [b][s][u]
__device__ __align__(16) float d_pre[B_*S_*U_];             // W1(encoded)+b1, rows b*64+s
__device__ __align__(16) float d_q[B_*U_];                  // attention query
__device__ __align__(16) float d_sc[B_*S_];                 // scores, row b*64+s
__device__ __align__(16) float d_xcat[B_*(U_+E_)];          // [ctx, Ed[tok]]
__device__ __align__(16) float d_Hall[T_*B_*U_];            // decoder hiddens, rows t*32+b
__device__ __align__(16) float d_logits_alt[T_*B_*V_];
// bf16 split operands (A: [M][3K] row-major;  B: [3K][N] k-major)
__device__ __align__(16) __nv_bfloat16 d_WfT3[(size_t)3*1024*VP_];
__device__ __align__(16) __nv_bfloat16 d_W1T3[3*1024*1024];
__device__ __align__(16) __nv_bfloat16 d_eWxT3[3*256*G_];
__device__ __align__(16) __nv_bfloat16 d_xembS[2048*768];
__device__ __align__(16) __nv_bfloat16 d_encS[(size_t)2048*3072];
__device__ __align__(16) __nv_bfloat16 d_HallS[512*3072];
__device__ unsigned int d_cnt;
__device__ volatile unsigned int d_gen;

__device__ __forceinline__ float sigm(float x) { return 1.f / (1.f + expf(-x)); }

// packed fp32x2 FMA (Blackwell): d += a * b elementwise on two packed floats
__device__ __forceinline__ void ffma2(unsigned long long& d, unsigned long long a, unsigned long long b) {
    asm("fma.rn.f32x2 %0, %1, %2, %0;" : "+l"(d) : "l"(a), "l"(b));
}
__device__ __forceinline__ float upsum(unsigned long long v) {
    union { unsigned long long u; float2 f; } x; x.u = v;
    return x.f.x + x.f.y;
}

// ---------------- software grid barrier (volatile-load spin, single atomic arrive) --
__device__ __forceinline__ void gbar() {
    __syncthreads();
    if (threadIdx.x == 0) {
        unsigned g = d_gen;
        __threadfence();
        if (atomicAdd(&d_cnt, 1u) == NB_ - 1u) {
            d_cnt = 0u;
            __threadfence();
            d_gen = g + 1u;
        } else {
            while (d_gen == g) __nanosleep(64);
        }
        __threadfence();
    }
    __syncthreads();
}

// ---------------- setup kernels ----------------
// embedding gather + bf16 split rows r=s*32+b -> [hi|lo|hi] over 3*256
__global__ void embed_split(const int* __restrict__ enc_in, const float* __restrict__ Ee) {
    int idx = blockIdx.x * 256 + threadIdx.x;
    int r = idx >> 8, e = idx & 255;
    int s = r >> 5, b = r & 31;
    float x = Ee[(size_t)enc_in[b * S_ + s] * E_ + e];
    __nv_bfloat16 hi = __float2bfloat16(x);
    __nv_bfloat16 lo = __float2bfloat16(x - __bfloat162float(hi));
    size_t base = (size_t)r * 768;
    d_xembS[base + e] = hi; d_xembS[base + 256 + e] = lo; d_xembS[base + 512 + e] = hi;
}

// A [M][K] fp32 -> [M][3K] bf16 = [hi|lo|hi]
__global__ void conv_splitA(const float* __restrict__ A, __nv_bfloat16* __restrict__ out, int kshift) {
    int idx = blockIdx.x * 256 + threadIdx.x;
    int K = 1 << kshift;
    int m = idx >> kshift, k = idx & (K - 1);
    float x = A[idx];
    __nv_bfloat16 hi = __float2bfloat16(x);
    __nv_bfloat16 lo = __float2bfloat16(x - __bfloat162float(hi));
    size_t base = (size_t)m * 3 * K;
    out[base + k] = hi; out[base + K + k] = lo; out[base + 2 * K + k] = hi;
}

// W [K][N] fp32 -> out [3K][NP] bf16 K-major = [hi ; hi ; lo] blocks
__global__ void conv_splitB_km(const float* __restrict__ W, __nv_bfloat16* __restrict__ out,
                               int K, int N, int NP) {
    int idx = blockIdx.x * 256 + threadIdx.x;
    int k = idx / NP, n = idx - k * NP;
    float x = (n < N) ? W[(size_t)k * N + n] : 0.f;
    __nv_bfloat16 hi = __float2bfloat16(x);
    __nv_bfloat16 lo = __float2bfloat16(x - __bfloat162float(hi));
    size_t p = (size_t)k * NP + n, sK = (size_t)K * NP;
    out[p] = hi; out[sK + p] = hi; out[2 * sK + p] = lo;
}

// ---------------- tensor-core bf16 GEMM ----------------
__device__ __forceinline__ void mma_bf16(float* c, const uint32_t* a, const uint32_t* b) {
    asm volatile("mma.sync.aligned.m16n8k16.row.col.f32.bf16.bf16.f32 "
        "{%0,%1,%2,%3},{%4,%5,%6,%7},{%8,%9},{%0,%1,%2,%3};"
        : "+f"(c[0]), "+f"(c[1]), "+f"(c[2]), "+f"(c[3])
        : "r"(a[0]), "r"(a[1]), "r"(a[2]), "r"(a[3]), "r"(b[0]), "r"(b[1]));
}
__device__ __forceinline__ void ldsm_x4(uint32_t* r, uint32_t addr) {
    asm volatile("ldmatrix.sync.aligned.m8n8.x4.shared.b16 {%0,%1,%2,%3}, [%4];"
        : "=r"(r[0]), "=r"(r[1]), "=r"(r[2]), "=r"(r[3]) : "r"(addr));
}
__device__ __forceinline__ void ldsm_x2_trans(uint32_t* r, uint32_t addr) {
    asm volatile("ldmatrix.sync.aligned.m8n8.x2.trans.shared.b16 {%0,%1}, [%2];"
        : "=r"(r[0]), "=r"(r[1]) : "r"(addr));
}

// C = A'[M,K3] @ B'[K3,N](k-major) + bias ; BM=128 BN=64 BK=32, 256 thr (4m x 2n warps)
// MODE 0: C[gm*ldC+gc]; MODE 1: logits scatter gm=t*32+b -> row b*16+t, stride Nreal
template<int MODE>
__global__ __launch_bounds__(256) void gemm_bf16(
    const __nv_bfloat16* __restrict__ A, const __nv_bfloat16* __restrict__ Bkm,
    const float* __restrict__ bias, float* __restrict__ C,
    int ldC, int Nreal, int K3, int ldB)
{
    __shared__ __nv_bfloat16 As[2][128 * 40];
    __shared__ __nv_bfloat16 Bs[2][32 * 72];
    const int tid = threadIdx.x;
    const int wid = tid >> 5, lane = tid & 31;
    const int gid = lane >> 2, tig = lane & 3;
    const int wm = wid & 3, wn = wid >> 2;
    const int m0 = blockIdx.y * 128, n0 = blockIdx.x * 64;

    const uint32_t asBase = (uint32_t)__cvta_generic_to_shared(&As[0][0]);
    const uint32_t bsBase = (uint32_t)__cvta_generic_to_shared(&Bs[0][0]);
    const int lquad = lane >> 3, l7 = lane & 7, l15 = lane & 15;
    const uint32_t aLane = (uint32_t)((((lquad & 1) * 8 + l7) * 80) + (lquad >> 1) * 16);

    float acc[2][4][4] = {};
    const int nkt = K3 >> 5;

    auto ldglobal = [&](int kt, int buf) {
#pragma unroll
        for (int i = 0; i < 2; i++) {
            int u4 = tid + i * 256;
            int row = u4 >> 2, c4 = u4 & 3;
            *(uint4*)&As[buf][row * 40 + c4 * 8] =
                *(const uint4*)&A[(size_t)(m0 + row) * K3 + kt * 32 + c4 * 8];
        }
        {
            int r = tid >> 3, c8 = tid & 7;
            *(uint4*)&Bs[buf][r * 72 + c8 * 8] =
                *(const uint4*)&Bkm[(size_t)(kt * 32 + r) * ldB + n0 + c8 * 8];
        }
    };

    ldglobal(0, 0);
    __syncthreads();
    for (int kt = 0; kt < nkt; kt++) {
        const int buf = kt & 1;
        if (kt + 1 < nkt) ldglobal(kt + 1, buf ^ 1);
#pragma unroll
        for (int ks = 0; ks < 2; ks++) {
            uint32_t a[2][4], b[4][2];
#pragma unroll
            for (int mi = 0; mi < 2; mi++)
                ldsm_x4(a[mi], asBase + (uint32_t)(buf * 128 * 80) +
                               (uint32_t)((wm * 32 + mi * 16) * 80 + ks * 32) + aLane);
#pragma unroll
            for (int ni = 0; ni < 4; ni++)
                ldsm_x2_trans(b[ni], bsBase + (uint32_t)(buf * 32 * 144) +
                              (uint32_t)(((ks * 16 + l15) * 72 + (wn * 32 + ni * 8)) * 2));
#pragma unroll
            for (int mi = 0; mi < 2; mi++)
#pragma unroll
                for (int ni = 0; ni < 4; ni++)
                    mma_bf16(acc[mi][ni], a[mi], b[ni]);
        }
        __syncthreads();
    }

#pragma unroll
    for (int mi = 0; mi < 2; mi++)
#pragma unroll
        for (int ni = 0; ni < 4; ni++) {
            int gm0 = m0 + wm * 32 + mi * 16 + gid;
            int gc0 = n0 + wn * 32 + ni * 8 + tig * 2;
#pragma unroll
            for (int e = 0; e < 4; e++) {
                int gm = gm0 + (e >> 1) * 8;
                int gc = gc0 + (e & 1);
                float v = acc[mi][ni][e];
                if (MODE == 1) {
                    if (gc < Nreal) {
                        int bb = gm & 31, tt = gm >> 5;
                        C[(size_t)(bb * T_ + tt) * Nreal + gc] = v + bias[gc];
                    }
                } else {
                    C[(size_t)gm * ldC + gc] = v + bias[gc];
                }
            }
        }
}

// ---------------- persistent encoder: 64 GRU steps, Wh slice in smem ----------------
// grid NB_=128, 128 threads. Block owns 8 u's; smem layout [ug][gate][k] (k contiguous).
__global__ __launch_bounds__(128) void enc_persist(const float* __restrict__ eWh,
                                                   const float* __restrict__ b_rec) {
    extern __shared__ float sw[];              // 8 * UGS floats
    const int nb = blockIdx.x, tid = threadIdx.x;
    for (int i = tid; i < 24576; i += 128) {
        int k = i / 24, c = i - k * 24;
        int g = c >> 3, ug = c & 7;
        sw[ug * UGS + g * 1024 + k] = eWh[(size_t)k * G_ + g * 1024 + nb * 8 + ug];
    }
    const int bp = tid & 15, ug = tid >> 4;
    const int b0 = bp * 2;
    const int u = nb * 8 + ug;
    const float brz = b_rec[u], brr = b_rec[U_ + u], brc = b_rec[2 * U_ + u];
    const float* swg = sw + ug * UGS;
    float hreg[2] = {0.f, 0.f};
    __syncthreads();

    for (int s = 0; s < S_; s++) {
        unsigned long long acc[2][3] = {};
        if (s > 0) {
            const float* hA = d_hbuf[s & 1] + b0 * U_;
            const float* hB = hA + U_;
#pragma unroll 4
            for (int k4 = 0; k4 < 256; k4++) {
                ulonglong2 a2 = *(const ulonglong2*)(hA + k4 * 4);
                ulonglong2 c2 = *(const ulonglong2*)(hB + k4 * 4);
#pragma unroll
                for (int g = 0; g < 3; g++) {
                    ulonglong2 w2v = *(const ulonglong2*)(swg + g * 1024 + k4 * 4);
                    ffma2(acc[0][g], a2.x, w2v.x); ffma2(acc[0][g], a2.y, w2v.y);
                    ffma2(acc[1][g], c2.x, w2v.x); ffma2(acc[1][g], c2.y, w2v.y);
                }
            }
        }
#pragma unroll
        for (int bi = 0; bi < 2; bi++) {
            int b = b0 + bi;
            const float* gx = d_gxall + ((size_t)s * 32 + b) * G_;
            float az = upsum(acc[bi][0]), ar = upsum(acc[bi][1]), ac = upsum(acc[bi][2]);
            float z = sigm(gx[u] + az + brz);
            float r = sigm(gx[U_ + u] + ar + brr);
            float c = tanhf(gx[2 * U_ + u] + r * (ac + brc));
            float h = z * hreg[bi] + (1.f - z) * c;
            hreg[bi] = h;
            d_hbuf[(s + 1) & 1][b * U_ + u] = h;
            d_enc[(size_t)b * (S_ * U_) + s * U_ + u] = h;
        }
        if (s < S_ - 1) gbar();
    }
}

// ---------------- persistent decoder: 16 steps x (q, scores, softmax+ctx, GRU) ------
__global__ __launch_bounds__(128) void dec_persist(
    const float* __restrict__ W2, const float* __restrict__ b2,
    const float* __restrict__ dWx,
    const float* __restrict__ Va, const float* __restrict__ bvp,
    const float* __restrict__ Ed, const int* __restrict__ teacher,
    const float* __restrict__ db_in, const float* __restrict__ db_rec)
{
    extern __shared__ float sm[];
    float* w2s = sm;                       // 8 * QS_  = 8256
    float* wds = sm + 8 * QS_;             // 8 * WGS  = 30784
    float* scs = wds + 8 * WGS;            // 2048
    float* red = scs + 2048;               // 1024
    const int nb = blockIdx.x, tid = threadIdx.x;

    for (int i = tid; i < 8192; i += 128) {
        int k = i >> 3, cq = i & 7;
        w2s[cq * QS_ + k] = W2[(size_t)k * U_ + nb * 8 + cq];
    }
    for (int i = tid; i < 30720; i += 128) {
        int k = i / 24, c = i - k * 24;
        int g = c >> 3, ug = c & 7;
        wds[ug * WGS + g * 1280 + k] = dWx[(size_t)k * G_ + g * 1024 + nb * 8 + ug];
    }
    const int bp = tid & 15, cq = tid >> 4;
    const int b0 = bp * 2;
    const int u = nb * 8 + cq;
    const float b2c = b2[u];
    const float biz = db_in[u], bir = db_in[U_ + u], bic = db_in[2 * U_ + u];
    const float brz = db_rec[u], brr = db_rec[U_ + u], brc = db_rec[2 * U_ + u];
    const float bv0 = bvp[0];
    const float* swq = w2s + cq * QS_;
    const float* swd = wds + cq * WGS;
    __syncthreads();

    for (int t = 0; t < T_; t++) {
        // ---- phase A: q = h @ W2 + b2 ----
        {
            const float* hsrc = (t == 0) ? d_hbuf[0] : d_hdec;
            const float* hA = hsrc + b0 * U_;
            const float* hB = hA + U_;
            unsigned long long a0 = 0ull, a1 = 0ull;
#pragma unroll 4
            for (int k4 = 0; k4 < 256; k4++) {
                ulonglong2 ha = *(const ulonglong2*)(hA + k4 * 4);
                ulonglong2 hb = *(const ulonglong2*)(hB + k4 * 4);
                ulonglong2 w2v = *(const ulonglong2*)(swq + k4 * 4);
                ffma2(a0, ha.x, w2v.x); ffma2(a0, ha.y, w2v.y);
                ffma2(a1, hb.x, w2v.x); ffma2(a1, hb.y, w2v.y);
            }
            d_q[b0 * U_ + u] = upsum(a0) + b2c;
            d_q[(b0 + 1) * U_ + u] = upsum(a1) + b2c;
        }
        gbar();
        // ---- phase B: scores ----
        {
            const int w = tid >> 5, lane = tid & 31;
#pragma unroll
            for (int rr = 0; rr < 4; rr++) {
                int row = nb * 16 + w * 4 + rr;       // row = b*64+s
                int b = row >> 6;
                const float* pr = d_pre + (size_t)row * U_;
                const float* qq = d_q + b * U_;
                float p = 0.f;
                for (int uu = lane; uu < U_; uu += 32)
                    p += tanhf(pr[uu] + qq[uu]) * Va[uu];
#pragma unroll
                for (int o = 16; o > 0; o >>= 1) p += __shfl_xor_sync(0xffffffffu, p, o);
                if (lane == 0) d_sc[row] = p + bv0;
            }
        }
        gbar();
        // ---- phase C1: softmax + ctx (+ Ed gather) ----
        {
            for (int i = tid; i < 2048; i += 128) scs[i] = d_sc[i];
            __syncthreads();
            if (tid < 32) {
                int b = tid;
                float m = scs[b * 64];
                for (int s = 1; s < 64; s++) m = fmaxf(m, scs[b * 64 + s]);
                float sum = 0.f;
                for (int s = 0; s < 64; s++) { float e = expf(scs[b * 64 + s] - m); scs[b * 64 + s] = e; sum += e; }
                float inv = 1.f / sum;
                for (int s = 0; s < 64; s++) scs[b * 64 + s] *= inv;
            }
            __syncthreads();
#pragma unroll
            for (int r = 0; r < 2; r++) {
                int task = tid + r * 128;
                int b = task & 31, qd = (task >> 5) & 1, sq = task >> 6;
                const float* ep = d_enc + (size_t)b * (S_ * U_) + nb * 8 + qd * 4;
                float4 a = {0.f, 0.f, 0.f, 0.f};
                for (int s = sq * 16; s < sq * 16 + 16; s++) {
                    float p = scs[b * 64 + s];
                    float4 ev = *(const float4*)(ep + (size_t)s * U_);
                    a.x += p * ev.x; a.y += p * ev.y; a.z += p * ev.z; a.w += p * ev.w;
                }
                *(float4*)&red[task * 4] = a;
            }
            __syncthreads();
            if (tid < 64) {
                int b = tid >> 1, qd = tid & 1;
                float4 s0 = *(float4*)&red[((0 * 64) + qd * 32 + b) * 4];
                float4 s1 = *(float4*)&red[((1 * 64) + qd * 32 + b) * 4];
                float4 s2 = *(float4*)&red[((2 * 64) + qd * 32 + b) * 4];
                float4 s3 = *(float4*)&red[((3 * 64) + qd * 32 + b) * 4];
                float4 o = {s0.x + s1.x + s2.x + s3.x, s0.y + s1.y + s2.y + s3.y,
                            s0.z + s1.z + s2.z + s3.z, s0.w + s1.w + s2.w + s3.w};
                *(float4*)&d_xcat[b * (U_ + E_) + nb * 8 + qd * 4] = o;
            }
            if (tid < 64) {
                int gi = nb * 64 + tid;           // 8192 total
                int b = gi >> 8, e = gi & 255;
                int tok = teacher[b * T_ + t];
                d_xcat[b * (U_ + E_) + U_ + e] = Ed[(size_t)tok * E_ + e];
            }
        }
        gbar();
        // ---- phase C2: xcat @ dWx + GRU gate (h0 = 0) ----
        {
            unsigned long long acc[2][3] = {};
            const float* xA = d_xcat + b0 * (U_ + E_);
            const float* xB = xA + (U_ + E_);
#pragma unroll 4
            for (int k4 = 0; k4 < 320; k4++) {
                ulonglong2 ha = *(const ulonglong2*)(xA + k4 * 4);
                ulonglong2 hb = *(const ulonglong2*)(xB + k4 * 4);
#pragma unroll
                for (int g = 0; g < 3; g++) {
                    ulonglong2 w2v = *(const ulonglong2*)(swd + g * 1280 + k4 * 4);
                    ffma2(acc[0][g], ha.x, w2v.x); ffma2(acc[0][g], ha.y, w2v.y);
                    ffma2(acc[1][g], hb.x, w2v.x); ffma2(acc[1][g], hb.y, w2v.y);
                }
            }
#pragma unroll
            for (int bi = 0; bi < 2; bi++) {
                int b = b0 + bi;
                float z = sigm(upsum(acc[bi][0]) + biz + brz);
                float r = sigm(upsum(acc[bi][1]) + bir + brr);
                float c = tanhf(upsum(acc[bi][2]) + bic + r * brc);
                float h = (1.f - z) * c;
                d_hdec[b * U_ + u] = h;
                d_Hall[((size_t)t * 32 + b) * U_ + u] = h;
            }
        }
        if (t < T_ - 1) gbar();
    }
}

// ---------------- argmax ----------------
__global__ void argmax_k(const float* __restrict__ logits, long long* outI, float* outF, int asFloat)
{
    const int row = blockIdx.x;
    const float* p = logits + (size_t)row * V_;
    const int tid = threadIdx.x;
    float best = -INFINITY; int bi = 0;
    for (int v = tid; v < V_; v += 256) {
        float val = p[v];
        if (val > best) { best = val; bi = v; }
    }
    __shared__ float bvs[256]; __shared__ int bis[256];
    bvs[tid] = best; bis[tid] = bi;
    __syncthreads();
    for (int st = 128; st > 0; st >>= 1) {
        if (tid < st) {
            float ov = bvs[tid + st]; int oi = bis[tid + st];
            if (ov > bvs[tid] || (ov == bvs[tid] && oi < bis[tid])) { bvs[tid] = ov; bis[tid] = oi; }
        }
        __syncthreads();
    }
    if (tid == 0) {
        if (asFloat) outF[row] = (float)bis[0];
        else         outI[row] = (long long)bis[0];
    }
}

// ---------------- launcher ----------------
static float* symaddr(const void* sym) {
    void* p = nullptr;
    cudaGetSymbolAddress(&p, sym);
    return (float*)p;
}

extern "C" void kernel_launch(void* const* d_in, const int* in_sizes, int n_in,
                              void* d_out, int out_size)
{
    const int s0 = (n_in >= 22) ? 4 : 2;
    const int*   enc_in  = (const int*)d_in[0];
    const int*   teacher = (const int*)d_in[1];
    const float* Ee      = (const float*)d_in[s0 + 0];
    const float* eWx     = (const float*)d_in[s0 + 1];
    const float* eWh     = (const float*)d_in[s0 + 2];
    const float* eb_in   = (const float*)d_in[s0 + 3];
    const float* eb_rec  = (const float*)d_in[s0 + 4];
    const float* Ed      = (const float*)d_in[s0 + 5];
    const float* dWx     = (const float*)d_in[s0 + 6];
    const float* db_in   = (const float*)d_in[s0 + 8];
    const float* db_rec  = (const float*)d_in[s0 + 9];
    const float* W1      = (const float*)d_in[s0 + 10];
    const float* b1      = (const float*)d_in[s0 + 11];
    const float* W2      = (const float*)d_in[s0 + 12];
    const float* b2      = (const float*)d_in[s0 + 13];
    const float* Va      = (const float*)d_in[s0 + 14];
    const float* bvp     = (const float*)d_in[s0 + 15];
    const float* Wf      = (const float*)d_in[s0 + 16];
    const float* bf      = (const float*)d_in[s0 + 17];

    float* encp  = symaddr(d_enc);
    float* prep  = symaddr(d_pre);
    float* Hall  = symaddr(d_Hall);
    float* lalt  = symaddr(d_logits_alt);
    float* gxall = symaddr(d_gxall);
    __nv_bfloat16* WfT3;  { void* p; cudaGetSymbolAddress(&p, d_WfT3);  WfT3  = (__nv_bfloat16*)p; }
    __nv_bfloat16* W1T3;  { void* p; cudaGetSymbolAddress(&p, d_W1T3);  W1T3  = (__nv_bfloat16*)p; }
    __nv_bfloat16* eWxT3; { void* p; cudaGetSymbolAddress(&p, d_eWxT3); eWxT3 = (__nv_bfloat16*)p; }
    __nv_bfloat16* xembS; { void* p; cudaGetSymbolAddress(&p, d_xembS); xembS = (__nv_bfloat16*)p; }
    __nv_bfloat16* encS;  { void* p; cudaGetSymbolAddress(&p, d_encS);  encS  = (__nv_bfloat16*)p; }
    __nv_bfloat16* HallS; { void* p; cudaGetSymbolAddress(&p, d_HallS); HallS = (__nv_bfloat16*)p; }

    // output convention
    const long long LOGN = (long long)B_ * T_ * V_;
    float* logits_dst = (float*)d_out;
    long long* predI = nullptr; float* predF = nullptr; int asFloat = 0;
    if ((long long)out_size == LOGN + 512) { predF = (float*)d_out + LOGN; asFloat = 1; }
    else if ((long long)out_size == LOGN + 1024) { predI = (long long*)((float*)d_out + LOGN); }
    else if (out_size == 512) { logits_dst = lalt; predI = (long long*)d_out; }

    const int ENC_SMEM = 8 * UGS * 4;
    const int DEC_SMEM = (8 * QS_ + 8 * WGS + 2048 + 1024) * 4;
    cudaFuncSetAttribute(enc_persist, cudaFuncAttributeMaxDynamicSharedMemorySize, ENC_SMEM);
    cudaFuncSetAttribute(dec_persist, cudaFuncAttributeMaxDynamicSharedMemorySize, DEC_SMEM);

    // weight prep (bf16 splits)
    conv_splitB_km<<<(E_ * G_) / 256, 256>>>(eWx, eWxT3, E_, G_, G_);
    conv_splitB_km<<<(U_ * U_) / 256, 256>>>(W1, W1T3, U_, U_, U_);
    conv_splitB_km<<<(U_ * VP_) / 256, 256>>>(Wf, WfT3, U_, V_, VP_);

    // encoder front: embed + gx (all steps, tensor cores)
    embed_split<<<2048, 256>>>(enc_in, Ee);
    gemm_bf16<0><<<dim3(G_ / 64, (S_ * B_) / 128), 256>>>(xembS, eWxT3, eb_in, gxall, G_, G_, 768, G_);

    // persistent encoder (single launch, 64 steps)
    enc_persist<<<NB_, 128, ENC_SMEM>>>(eWh, eb_rec);

    // pre_enc = encoded @ W1 + b1
    conv_splitA<<<(B_ * S_ * U_) / 256, 256>>>(encp, encS, 10);
    gemm_bf16<0><<<dim3(U_ / 64, (B_ * S_) / 128), 256>>>(encS, W1T3, b1, prep, U_, U_, 3072, U_);

    // persistent decoder (single launch, 16 steps)
    dec_persist<<<NB_, 128, DEC_SMEM>>>(W2, b2, dWx, Va, bvp, Ed, teacher, db_in, db_rec);

    // logits = Hall @ Wf + bf
    conv_splitA<<<(T_ * B_ * U_) / 256, 256>>>(Hall, HallS, 10);
    gemm_bf16<1><<<dim3(VP_ / 64, (T_ * B_) / 128), 256>>>(HallS, WfT3, bf, logits_dst, 0, V_, 3072, VP_);

    if (predI || predF) argmax_k<<<T_ * B_, 256>>>(logits_dst, predI, predF, asFloat);
}

// round 7
// speedup vs baseline: 1.5208x; 1.5208x over previous
#include <cuda_runtime.h>
#include <cuda_bf16.h>
#include <math.h>
#include <stdint.h>

#define B_ 32
#define S_ 64
#define T_ 16
#define U_ 1024
#define E_ 256
#define V_ 20200
#define G_ 3072          /* 3*U */
#define VP_ 20224        /* V padded to 64 */

// ---------------- device scratch ----------------
__device__ __align__(16) float d_gxall[S_*B_*G_];           // [s*32+b][3072]
__device__ __align__(16) float d_hbuf[2][B_*U_];            // encoder hidden ping-pong
__device__ __align__(16) float d_hdec[B_*U_];               // decoder hidden
__device__ __align__(16) float d_enc[B_*S_*U_];             // encoded [b][s][u]
__device__ __align__(16) float d_pre[B_*S_*U_];             // W1(encoded)+b1, rows b*64+s
__device__ __align__(16) float d_q[B_*U_];                  // attention query
__device__ __align__(16) float d_gpart[8][B_*G_];           // split-K partials
__device__ __align__(16) float d_xcat[B_*(U_+E_)];          // [ctx, Ed[tok]]
__device__ __align__(16) float d_Hall[T_*B_*U_];            // decoder hiddens, rows t*32+b
__device__ __align__(16) float d_logits_alt[T_*B_*V_];
__device__ __align__(16) float d_WhP[U_*G_];                // eWh cols permuted (u*3+g)
__device__ __align__(16) float d_dWxP[(U_+E_)*G_];          // dWx cols permuted
// bf16 split operands (A: [M][3K] row-major;  B: [3K][NP] K-major)
__device__ __align__(16) __nv_bfloat16 d_WfT3[(size_t)3*1024*VP_];
__device__ __align__(16) __nv_bfloat16 d_W1T3[3*1024*1024];
__device__ __align__(16) __nv_bfloat16 d_eWxT3[3*256*G_];
__device__ __align__(16) __nv_bfloat16 d_xembS[2048*768];
__device__ __align__(16) __nv_bfloat16 d_encS[(size_t)2048*3072];   // rows b*64+s
__device__ __align__(16) __nv_bfloat16 d_HallS[512*3072];           // rows t*32+b
__device__ unsigned int d_ctr[3*64];   // arrival counters (self-resetting)

__device__ __forceinline__ float sigm(float x) { return 1.f / (1.f + expf(-x)); }

// ---------------- setup kernels ----------------
// permute W[rows][3072] columns: out[k][u*3+g] = W[k][g*1024+u]
__global__ void perm3(const float* __restrict__ W, float* __restrict__ out) {
    int idx = blockIdx.x * 256 + threadIdx.x;
    int k = idx / G_, c = idx - k * G_;
    int u = c / 3, g = c - u * 3;
    out[idx] = W[(size_t)k * G_ + g * U_ + u];
}

// embedding gather + bf16 split: row r=s*32+b -> [hi|lo|hi] over 3*256
__global__ void embed_split(const int* __restrict__ enc_in, const float* __restrict__ Ee) {
    int idx = blockIdx.x * 256 + threadIdx.x;
    int r = idx >> 8, e = idx & 255;
    int s = r >> 5, b = r & 31;
    float x = Ee[(size_t)enc_in[b * S_ + s] * E_ + e];
    __nv_bfloat16 hi = __float2bfloat16(x);
    __nv_bfloat16 lo = __float2bfloat16(x - __bfloat162float(hi));
    size_t base = (size_t)r * 768;
    d_xembS[base + e] = hi; d_xembS[base + 256 + e] = lo; d_xembS[base + 512 + e] = hi;
}

// W [K][N] fp32 -> out [3K][NP] bf16 K-major = [hi ; hi ; lo], 8 cols/thread, vector I/O
__global__ void conv_splitB_v8(const float* __restrict__ W, __nv_bfloat16* __restrict__ out,
                               int K, int N, int NP) {
    int idx = blockIdx.x * 256 + threadIdx.x;
    int per = NP >> 3;
    int k = idx / per, n = (idx - k * per) * 8;
    if (k >= K) return;
    float v[8];
    if (n + 8 <= N) {
        float4 a = *(const float4*)&W[(size_t)k * N + n];
        float4 b = *(const float4*)&W[(size_t)k * N + n + 4];
        v[0]=a.x; v[1]=a.y; v[2]=a.z; v[3]=a.w; v[4]=b.x; v[5]=b.y; v[6]=b.z; v[7]=b.w;
    } else {
#pragma unroll
        for (int j = 0; j < 8; j++) v[j] = (n + j < N) ? W[(size_t)k * N + n + j] : 0.f;
    }
    __nv_bfloat16 hi[8], lo[8];
#pragma unroll
    for (int j = 0; j < 8; j++) {
        hi[j] = __float2bfloat16(v[j]);
        lo[j] = __float2bfloat16(v[j] - __bfloat162float(hi[j]));
    }
    size_t p = (size_t)k * NP + n, sK = (size_t)K * NP;
    *(uint4*)&out[p]          = *(uint4*)hi;
    *(uint4*)&out[sK + p]     = *(uint4*)hi;
    *(uint4*)&out[2 * sK + p] = *(uint4*)lo;
}

// ---------------- tensor-core bf16 GEMM (K-major B; validated rounds 4-6) ----------
__device__ __forceinline__ void mma_bf16(float* c, const uint32_t* a, const uint32_t* b) {
    asm volatile("mma.sync.aligned.m16n8k16.row.col.f32.bf16.bf16.f32 "
        "{%0,%1,%2,%3},{%4,%5,%6,%7},{%8,%9},{%0,%1,%2,%3};"
        : "+f"(c[0]), "+f"(c[1]), "+f"(c[2]), "+f"(c[3])
        : "r"(a[0]), "r"(a[1]), "r"(a[2]), "r"(a[3]), "r"(b[0]), "r"(b[1]));
}
__device__ __forceinline__ void ldsm_x4(uint32_t* r, uint32_t addr) {
    asm volatile("ldmatrix.sync.aligned.m8n8.x4.shared.b16 {%0,%1,%2,%3}, [%4];"
        : "=r"(r[0]), "=r"(r[1]), "=r"(r[2]), "=r"(r[3]) : "r"(addr));
}
__device__ __forceinline__ void ldsm_x2_trans(uint32_t* r, uint32_t addr) {
    asm volatile("ldmatrix.sync.aligned.m8n8.x2.trans.shared.b16 {%0,%1}, [%2];"
        : "=r"(r[0]), "=r"(r[1]) : "r"(addr));
}

// C = A'[M,K3] @ B'[K3,N](K-major) + bias ; BM=128 BN=64 BK=32, 256 thr (4m x 2n warps)
// MODE 0: C[gm*ldC+gc]; MODE 1: logits scatter gm=t*32+b -> row b*16+t, stride Nreal
template<int MODE>
__global__ __launch_bounds__(256) void gemm_bf16(
    const __nv_bfloat16* __restrict__ A, const __nv_bfloat16* __restrict__ Bkm,
    const float* __restrict__ bias, float* __restrict__ C,
    int ldC, int Nreal, int K3, int ldB)
{
    __shared__ __nv_bfloat16 As[2][128 * 40];
    __shared__ __nv_bfloat16 Bs[2][32 * 72];
    const int tid = threadIdx.x;
    const int wid = tid >> 5, lane = tid & 31;
    const int gid = lane >> 2, tig = lane & 3;
    const int wm = wid & 3, wn = wid >> 2;
    const int m0 = blockIdx.y * 128, n0 = blockIdx.x * 64;

    const uint32_t asBase = (uint32_t)__cvta_generic_to_shared(&As[0][0]);
    const uint32_t bsBase = (uint32_t)__cvta_generic_to_shared(&Bs[0][0]);
    const int lquad = lane >> 3, l7 = lane & 7, l15 = lane & 15;
    const uint32_t aLane = (uint32_t)((((lquad & 1) * 8 + l7) * 80) + (lquad >> 1) * 16);

    float acc[2][4][4] = {};
    const int nkt = K3 >> 5;

    auto ldglobal = [&](int kt, int buf) {
#pragma unroll
        for (int i = 0; i < 2; i++) {
            int u4 = tid + i * 256;
            int row = u4 >> 2, c4 = u4 & 3;
            *(uint4*)&As[buf][row * 40 + c4 * 8] =
                *(const uint4*)&A[(size_t)(m0 + row) * K3 + kt * 32 + c4 * 8];
        }
        {
            int r = tid >> 3, c8 = tid & 7;
            *(uint4*)&Bs[buf][r * 72 + c8 * 8] =
                *(const uint4*)&Bkm[(size_t)(kt * 32 + r) * ldB + n0 + c8 * 8];
        }
    };

    ldglobal(0, 0);
    __syncthreads();
    for (int kt = 0; kt < nkt; kt++) {
        const int buf = kt & 1;
        if (kt + 1 < nkt) ldglobal(kt + 1, buf ^ 1);
#pragma unroll
        for (int ks = 0; ks < 2; ks++) {
            uint32_t a[2][4], b[4][2];
#pragma unroll
            for (int mi = 0; mi < 2; mi++)
                ldsm_x4(a[mi], asBase + (uint32_t)(buf * 128 * 80) +
                               (uint32_t)((wm * 32 + mi * 16) * 80 + ks * 32) + aLane);
#pragma unroll
            for (int ni = 0; ni < 4; ni++)
                ldsm_x2_trans(b[ni], bsBase + (uint32_t)(buf * 32 * 144) +
                              (uint32_t)(((ks * 16 + l15) * 72 + (wn * 32 + ni * 8)) * 2));
#pragma unroll
            for (int mi = 0; mi < 2; mi++)
#pragma unroll
                for (int ni = 0; ni < 4; ni++)
                    mma_bf16(acc[mi][ni], a[mi], b[ni]);
        }
        __syncthreads();
    }

#pragma unroll
    for (int mi = 0; mi < 2; mi++)
#pragma unroll
        for (int ni = 0; ni < 4; ni++) {
            int gm0 = m0 + wm * 32 + mi * 16 + gid;
            int gc0 = n0 + wn * 32 + ni * 8 + tig * 2;
#pragma unroll
            for (int e = 0; e < 4; e++) {
                int gm = gm0 + (e >> 1) * 8;
                int gc = gc0 + (e & 1);
                float v = acc[mi][ni][e];
                if (MODE == 1) {
                    if (gc < Nreal) {
                        int bb = gm & 31, tt = gm >> 5;
                        C[(size_t)(bb * T_ + tt) * Nreal + gc] = v + bias[gc];
                    }
                } else {
                    C[(size_t)gm * ldC + gc] = v + bias[gc];
                }
            }
        }
}

// ---------------- fused recurrence step: split-K GEMM + last-block gate fixup ----
// BM=32, BK=16, 128 threads (TX=16, TY=8, TM=4).
// GATE 0: q = h@W2 + b2 -> qout    GATE 1: encoder GRU    GATE 2: decoder GRU (h0=0)
template<int BN, int TN, int NKC, int GATE>
__global__ __launch_bounds__(128) void step_gemm(
    const float* __restrict__ A, const float* __restrict__ Bm,
    const float* __restrict__ xb, const float* __restrict__ hb,
    const float* __restrict__ hin, float* __restrict__ hout,
    float* __restrict__ extra, float* __restrict__ part,
    float* __restrict__ qout, unsigned int* __restrict__ ctr,
    int N, int K, int sidx)
{
    __shared__ float As[16][32];
    __shared__ float Bs[16][BN];
    __shared__ int doneflag;
    const int tid = threadIdx.x;
    const int tx = tid & 15, ty = tid >> 4;
    const int n0 = blockIdx.x * BN;
    const int z = blockIdx.z;
    const int k0 = z * NKC * 16;

    float acc[4][TN];
#pragma unroll
    for (int i = 0; i < 4; i++)
#pragma unroll
        for (int j = 0; j < TN; j++) acc[i][j] = 0.f;

    for (int kt = 0; kt < NKC; kt++) {
#pragma unroll
        for (int ii = tid; ii < 512; ii += 128) {
            int k = ii & 15, m = ii >> 4;
            As[k][m] = A[(size_t)m * K + k0 + kt * 16 + k];
        }
        for (int ii = tid; ii < 16 * BN; ii += 128) {
            int k = ii / BN, n = ii - k * BN;
            Bs[k][n] = Bm[(size_t)(k0 + kt * 16 + k) * N + n0 + n];
        }
        __syncthreads();
#pragma unroll
        for (int kk = 0; kk < 16; kk++) {
            float4 av = *reinterpret_cast<const float4*>(&As[kk][ty * 4]);
            float a[4] = {av.x, av.y, av.z, av.w};
#pragma unroll
            for (int j = 0; j < TN; j++) {
                float bv = Bs[kk][tx * TN + j];
#pragma unroll
                for (int i = 0; i < 4; i++) acc[i][j] += a[i] * bv;
            }
        }
        __syncthreads();
    }
    // write partials
#pragma unroll
    for (int i = 0; i < 4; i++) {
        int gm = ty * 4 + i;
#pragma unroll
        for (int j = 0; j < TN; j++)
            part[((size_t)(z * 32 + gm)) * N + n0 + tx * TN + j] = acc[i][j];
    }
    __threadfence();
    __syncthreads();
    if (tid == 0) {
        unsigned int prev = atomicAdd(&ctr[blockIdx.x], 1u);
        doneflag = (prev == 7u);
        if (prev == 7u) ctr[blockIdx.x] = 0u;   // self-reset for next launch
    }
    __syncthreads();
    if (!doneflag) return;
    __threadfence();   // acquire: all partials visible

    if (GATE == 0) {
#pragma unroll
        for (int i = 0; i < 16; i++) {
            int idx = tid + i * 128;           // 2048 = 64 cols x 32 b
            int b = idx & 31, nl = idx >> 5;
            int n = n0 + nl;
            float s = 0.f;
#pragma unroll
            for (int zz = 0; zz < 8; zz++) s += part[((size_t)(zz * 32 + b)) * N + n];
            qout[b * U_ + n] = s + hb[n];
        }
    } else {
        const int u0 = n0 / 3;                 // BN=48 -> 16 u's
#pragma unroll
        for (int i = 0; i < 4; i++) {
            int idx = tid + i * 128;           // 512 = 16 u x 32 b
            int b = idx & 31, ul = idx >> 5;
            int u = u0 + ul;
            float g[3];
#pragma unroll
            for (int gg = 0; gg < 3; gg++) {
                float s = 0.f;
#pragma unroll
                for (int zz = 0; zz < 8; zz++)
                    s += part[((size_t)(zz * 32 + b)) * N + n0 + ul * 3 + gg];
                g[gg] = s;
            }
            float h;
            if (GATE == 1) {
                const float* gx = xb + (size_t)b * G_;
                float zg = sigm(gx[u] + g[0] + hb[u]);
                float rg = sigm(gx[U_ + u] + g[1] + hb[U_ + u]);
                float cg = tanhf(gx[2 * U_ + u] + rg * (g[2] + hb[2 * U_ + u]));
                h = zg * hin[b * U_ + u] + (1.f - zg) * cg;
                hout[b * U_ + u] = h;
                extra[(size_t)b * (S_ * U_) + u] = h;      // extra = d_enc + s*U_
                // bf16 split archive row b*64+s
                __nv_bfloat16 hi = __float2bfloat16(h);
                __nv_bfloat16 lo = __float2bfloat16(h - __bfloat162float(hi));
                size_t ar = ((size_t)b * 64 + sidx) * 3072;
                d_encS[ar + u] = hi; d_encS[ar + 1024 + u] = lo; d_encS[ar + 2048 + u] = hi;
            } else {
                float zg = sigm(g[0] + xb[u] + hb[u]);
                float rg = sigm(g[1] + xb[U_ + u] + hb[U_ + u]);
                float cg = tanhf(g[2] + xb[2 * U_ + u] + rg * hb[2 * U_ + u]);
                h = (1.f - zg) * cg;
                hout[b * U_ + u] = h;                       // d_hdec
                extra[(size_t)b * U_ + u] = h;              // d_Hall + t*B*U
                __nv_bfloat16 hi = __float2bfloat16(h);
                __nv_bfloat16 lo = __float2bfloat16(h - __bfloat162float(hi));
                size_t ar = ((size_t)sidx * 32 + b) * 3072;
                d_HallS[ar + u] = hi; d_HallS[ar + 1024 + u] = lo; d_HallS[ar + 2048 + u] = hi;
            }
        }
    }
}

// ---------------- attention + context + embed concat (block per batch row) ----------------
__global__ void attn_ctx(const float* __restrict__ Va, const float* __restrict__ bvp,
                         const float* __restrict__ Ed, const int* __restrict__ teacher, int t)
{
    const int b = blockIdx.x, tid = threadIdx.x;
    __shared__ float qs[U_];
    __shared__ float sc[S_];
    __shared__ float inv_s;

    for (int u = tid; u < U_; u += 256) qs[u] = d_q[b * U_ + u];
    __syncthreads();

    const int w = tid >> 5, lane = tid & 31;
    for (int s = w; s < S_; s += 8) {
        const float* pr = d_pre + (size_t)b * (S_ * U_) + (size_t)s * U_;
        float p = 0.f;
        for (int u = lane; u < U_; u += 32) p += tanhf(pr[u] + qs[u]) * Va[u];
#pragma unroll
        for (int o = 16; o > 0; o >>= 1) p += __shfl_xor_sync(0xffffffffu, p, o);
        if (lane == 0) sc[s] = p + bvp[0];
    }
    __syncthreads();

    if (tid == 0) {
        float m = sc[0];
        for (int s = 1; s < S_; s++) m = fmaxf(m, sc[s]);
        float sum = 0.f;
        for (int s = 0; s < S_; s++) { float e = expf(sc[s] - m); sc[s] = e; sum += e; }
        inv_s = 1.f / sum;
    }
    __syncthreads();

    const float inv = inv_s;
    for (int u = tid; u < U_; u += 256) {
        float a = 0.f;
        const float* eb = d_enc + (size_t)b * (S_ * U_) + u;
#pragma unroll 8
        for (int s = 0; s < S_; s++) a += sc[s] * eb[(size_t)s * U_];
        d_xcat[(size_t)b * (U_ + E_) + u] = a * inv;
    }
    const int tok = teacher[b * T_ + t];
    if (tid < E_) d_xcat[(size_t)b * (U_ + E_) + U_ + tid] = Ed[(size_t)tok * E_ + tid];
}

// ---------------- argmax (first-max tie rule) ----------------
__global__ void argmax_k(const float* __restrict__ logits, long long* outI, float* outF, int asFloat)
{
    const int row = blockIdx.x;          // row = b*16+t
    const float* p = logits + (size_t)row * V_;
    const int tid = threadIdx.x;
    float best = -INFINITY; int bi = 0;
    for (int v = tid; v < V_; v += 256) {
        float val = p[v];
        if (val > best) { best = val; bi = v; }
    }
    __shared__ float bvs[256]; __shared__ int bis[256];
    bvs[tid] = best; bis[tid] = bi;
    __syncthreads();
    for (int st = 128; st > 0; st >>= 1) {
        if (tid < st) {
            float ov = bvs[tid + st]; int oi = bis[tid + st];
            if (ov > bvs[tid] || (ov == bvs[tid] && oi < bis[tid])) { bvs[tid] = ov; bis[tid] = oi; }
        }
        __syncthreads();
    }
    if (tid == 0) {
        if (asFloat) outF[row] = (float)bis[0];
        else         outI[row] = (long long)bis[0];
    }
}

// ---------------- launcher ----------------
static float* symaddr(const void* sym) {
    void* p = nullptr;
    cudaGetSymbolAddress(&p, sym);
    return (float*)p;
}

extern "C" void kernel_launch(void* const* d_in, const int* in_sizes, int n_in,
                              void* d_out, int out_size)
{
    const int s0 = (n_in >= 22) ? 4 : 2;
    const int*   enc_in  = (const int*)d_in[0];
    const int*   teacher = (const int*)d_in[1];
    const float* Ee      = (const float*)d_in[s0 + 0];
    const float* eWx     = (const float*)d_in[s0 + 1];
    const float* eWh     = (const float*)d_in[s0 + 2];
    const float* eb_in   = (const float*)d_in[s0 + 3];
    const float* eb_rec  = (const float*)d_in[s0 + 4];
    const float* Ed      = (const float*)d_in[s0 + 5];
    const float* dWx     = (const float*)d_in[s0 + 6];
    const float* db_in   = (const float*)d_in[s0 + 8];
    const float* db_rec  = (const float*)d_in[s0 + 9];
    const float* W1      = (const float*)d_in[s0 + 10];
    const float* b1      = (const float*)d_in[s0 + 11];
    const float* W2      = (const float*)d_in[s0 + 12];
    const float* b2      = (const float*)d_in[s0 + 13];
    const float* Va      = (const float*)d_in[s0 + 14];
    const float* bvp     = (const float*)d_in[s0 + 15];
    const float* Wf      = (const float*)d_in[s0 + 16];
    const float* bf      = (const float*)d_in[s0 + 17];

    float* hbase = symaddr(d_hbuf);
    float* hdec  = symaddr(d_hdec);
    float* encp  = symaddr(d_enc);
    float* prep  = symaddr(d_pre);
    float* qp    = symaddr(d_q);
    float* gpart = symaddr(d_gpart);
    float* xcat  = symaddr(d_xcat);
    float* Hall  = symaddr(d_Hall);
    float* lalt  = symaddr(d_logits_alt);
    float* gxall = symaddr(d_gxall);
    float* WhP   = symaddr(d_WhP);
    float* dWxP  = symaddr(d_dWxP);
    unsigned int* ctr; { void* p; cudaGetSymbolAddress(&p, d_ctr); ctr = (unsigned int*)p; }
    __nv_bfloat16* WfT3;  { void* p; cudaGetSymbolAddress(&p, d_WfT3);  WfT3  = (__nv_bfloat16*)p; }
    __nv_bfloat16* W1T3;  { void* p; cudaGetSymbolAddress(&p, d_W1T3);  W1T3  = (__nv_bfloat16*)p; }
    __nv_bfloat16* eWxT3; { void* p; cudaGetSymbolAddress(&p, d_eWxT3); eWxT3 = (__nv_bfloat16*)p; }
    __nv_bfloat16* xembS; { void* p; cudaGetSymbolAddress(&p, d_xembS); xembS = (__nv_bfloat16*)p; }
    __nv_bfloat16* encS;  { void* p; cudaGetSymbolAddress(&p, d_encS);  encS  = (__nv_bfloat16*)p; }
    __nv_bfloat16* HallS; { void* p; cudaGetSymbolAddress(&p, d_HallS); HallS = (__nv_bfloat16*)p; }

    // output convention
    const long long LOGN = (long long)B_ * T_ * V_;
    float* logits_dst = (float*)d_out;
    long long* predI = nullptr; float* predF = nullptr; int asFloat = 0;
    if ((long long)out_size == LOGN + 512) { predF = (float*)d_out + LOGN; asFloat = 1; }
    else if ((long long)out_size == LOGN + 1024) { predI = (long long*)((float*)d_out + LOGN); }
    else if (out_size == 512) { logits_dst = lalt; predI = (long long*)d_out; }

    cudaMemsetAsync(hbase, 0, (size_t)B_ * U_ * sizeof(float));

    // weight prep
    perm3<<<U_ * G_ / 256, 256>>>(eWh, WhP);
    perm3<<<(U_ + E_) * G_ / 256, 256>>>(dWx, dWxP);
    conv_splitB_v8<<<(E_ * (G_ / 8) + 255) / 256, 256>>>(eWx, eWxT3, E_, G_, G_);
    conv_splitB_v8<<<(U_ * (U_ / 8) + 255) / 256, 256>>>(W1, W1T3, U_, U_, U_);
    conv_splitB_v8<<<(U_ * (VP_ / 8) + 255) / 256, 256>>>(Wf, WfT3, U_, V_, VP_);

    // encoder front: embed + gx (all steps, tensor cores)
    embed_split<<<2048, 256>>>(enc_in, Ee);
    gemm_bf16<0><<<dim3(G_ / 64, (S_ * B_) / 128), 256>>>(xembS, eWxT3, eb_in, gxall, G_, G_, 768, G_);

    // encoder recurrence: one fused launch per step
    for (int s = 0; s < S_; s++) {
        float* hin  = hbase + (size_t)(s & 1) * B_ * U_;
        float* hout = hbase + (size_t)((s + 1) & 1) * B_ * U_;
        step_gemm<48,3,8,1><<<dim3(G_ / 48, 1, 8), 128>>>(
            hin, WhP, gxall + (size_t)s * B_ * G_, eb_rec,
            hin, hout, encp + (size_t)s * U_, gpart, nullptr, ctr, G_, U_, s);
    }

    // pre_enc = encoded @ W1 + b1 (A archive written by encoder gates)
    gemm_bf16<0><<<dim3(U_ / 64, (B_ * S_) / 128), 256>>>(encS, W1T3, b1, prep, U_, U_, 3072, U_);

    // decoder: 3 launches per step
    for (int t = 0; t < T_; t++) {
        const float* hd = (t == 0) ? hbase : hdec;
        step_gemm<64,4,8,0><<<dim3(U_ / 64, 1, 8), 128>>>(
            hd, W2, nullptr, b2, nullptr, nullptr, nullptr, gpart, qp, ctr + 64, U_, U_, t);
        attn_ctx<<<B_, 256>>>(Va, bvp, Ed, teacher, t);
        step_gemm<48,3,10,2><<<dim3(G_ / 48, 1, 8), 128>>>(
            xcat, dWxP, db_in, db_rec, nullptr, hdec,
            Hall + (size_t)t * B_ * U_, gpart, nullptr, ctr + 128, G_, U_ + E_, t);
    }

    // logits = Hall @ Wf + bf (A archive written by decoder gates)
    gemm_bf16<1><<<dim3(VP_ / 64, (T_ * B_) / 128), 256>>>(HallS, WfT3, bf, logits_dst, 0, V_, 3072, VP_);

    if (predI || predF) argmax_k<<<T_ * B_, 256>>>(logits_dst, predI, predF, asFloat);
}

// round 9
// speedup vs baseline: 1.5463x; 1.0168x over previous
#include <cuda_runtime.h>
#include <cuda_bf16.h>
#include <math.h>
#include <stdint.h>

#define B_ 32
#define S_ 64
#define T_ 16
#define U_ 1024
#define E_ 256
#define V_ 20200
#define G_ 3072
#define VP_ 20224

// ---------------- device scratch ----------------
__device__ __align__(16) float d_gxall[S_*B_*G_];
__device__ __align__(16) float d_hbuf[2][B_*U_];
__device__ __align__(16) float d_hdec[B_*U_];
__device__ __align__(16) float d_enc[B_*S_*U_];
__device__ __align__(16) float d_pre[B_*S_*U_];
__device__ __align__(16) float d_q[B_*U_];
__device__ __align__(16) float d_gpart[8][B_*G_];
__device__ __align__(16) float d_xcat[B_*(U_+E_)];
__device__ __align__(16) float d_Hall[T_*B_*U_];
__device__ __align__(16) float d_logits_alt[T_*B_*V_];
__device__ __align__(16) float d_WhP[U_*G_];
__device__ __align__(16) float d_dWxP[(U_+E_)*G_];
__device__ __align__(16) __nv_bfloat16 d_WfT3[(size_t)3*1024*VP_];
__device__ __align__(16) __nv_bfloat16 d_W1T3[3*1024*1024];
__device__ __align__(16) __nv_bfloat16 d_eWxT3[3*256*G_];
__device__ __align__(16) __nv_bfloat16 d_xembS[2048*768];
__device__ __align__(16) __nv_bfloat16 d_encS[(size_t)2048*3072];   // rows b*64+s
__device__ __align__(16) __nv_bfloat16 d_HallS[512*3072];           // rows t*32+b
__device__ unsigned int d_ctr[3*64];

__device__ __forceinline__ float sigm(float x) { return 1.f / (1.f + expf(-x)); }

// ---------------- setup kernels ----------------
__global__ void perm3(const float* __restrict__ W, float* __restrict__ out) {
    int idx = blockIdx.x * 256 + threadIdx.x;
    int k = idx / G_, c = idx - k * G_;
    int u = c / 3, g = c - u * 3;
    out[idx] = W[(size_t)k * G_ + g * U_ + u];
}

__global__ void embed_split(const int* __restrict__ enc_in, const float* __restrict__ Ee) {
    int idx = blockIdx.x * 256 + threadIdx.x;
    int r = idx >> 8, e = idx & 255;
    int s = r >> 5, b = r & 31;
    float x = Ee[(size_t)enc_in[b * S_ + s] * E_ + e];
    __nv_bfloat16 hi = __float2bfloat16(x);
    __nv_bfloat16 lo = __float2bfloat16(x - __bfloat162float(hi));
    size_t base = (size_t)r * 768;
    d_xembS[base + e] = hi; d_xembS[base + 256 + e] = lo; d_xembS[base + 512 + e] = hi;
}

__global__ void conv_splitB_v8(const float* __restrict__ W, __nv_bfloat16* __restrict__ out,
                               int K, int N, int NP) {
    int idx = blockIdx.x * 256 + threadIdx.x;
    int per = NP >> 3;
    int k = idx / per, n = (idx - k * per) * 8;
    if (k >= K) return;
    float v[8];
    if (n + 8 <= N) {
        float4 a = *(const float4*)&W[(size_t)k * N + n];
        float4 b = *(const float4*)&W[(size_t)k * N + n + 4];
        v[0]=a.x; v[1]=a.y; v[2]=a.z; v[3]=a.w; v[4]=b.x; v[5]=b.y; v[6]=b.z; v[7]=b.w;
    } else {
#pragma unroll
        for (int j = 0; j < 8; j++) v[j] = (n + j < N) ? W[(size_t)k * N + n + j] : 0.f;
    }
    __nv_bfloat16 hi[8], lo[8];
#pragma unroll
    for (int j = 0; j < 8; j++) {
        hi[j] = __float2bfloat16(v[j]);
        lo[j] = __float2bfloat16(v[j] - __bfloat162float(hi[j]));
    }
    size_t p = (size_t)k * NP + n, sK = (size_t)K * NP;
    *(uint4*)&out[p]          = *(uint4*)hi;
    *(uint4*)&out[sK + p]     = *(uint4*)hi;
    *(uint4*)&out[2 * sK + p] = *(uint4*)lo;
}

// ---------------- tensor-core bf16 GEMM ----------------
__device__ __forceinline__ void mma_bf16(float* c, const uint32_t* a, const uint32_t* b) {
    asm volatile("mma.sync.aligned.m16n8k16.row.col.f32.bf16.bf16.f32 "
        "{%0,%1,%2,%3},{%4,%5,%6,%7},{%8,%9},{%0,%1,%2,%3};"
        : "+f"(c[0]), "+f"(c[1]), "+f"(c[2]), "+f"(c[3])
        : "r"(a[0]), "r"(a[1]), "r"(a[2]), "r"(a[3]), "r"(b[0]), "r"(b[1]));
}
__device__ __forceinline__ void ldsm_x4(uint32_t* r, uint32_t addr) {
    asm volatile("ldmatrix.sync.aligned.m8n8.x4.shared.b16 {%0,%1,%2,%3}, [%4];"
        : "=r"(r[0]), "=r"(r[1]), "=r"(r[2]), "=r"(r[3]) : "r"(addr));
}
__device__ __forceinline__ void ldsm_x2_trans(uint32_t* r, uint32_t addr) {
    asm volatile("ldmatrix.sync.aligned.m8n8.x2.trans.shared.b16 {%0,%1}, [%2];"
        : "=r"(r[0]), "=r"(r[1]) : "r"(addr));
}

// MODE 0: C[gm*ldC+gc]=..; MODE 1: logits scatter, global row = mofs+gm = t*32+b -> row b*16+t
template<int MODE>
__global__ __launch_bounds__(256) void gemm_bf16(
    const __nv_bfloat16* __restrict__ A, const __nv_bfloat16* __restrict__ Bkm,
    const float* __restrict__ bias, float* __restrict__ C,
    int ldC, int Nreal, int K3, int ldB, int mofs)
{
    __shared__ __nv_bfloat16 As[2][128 * 40];
    __shared__ __nv_bfloat16 Bs[2][32 * 72];
    const int tid = threadIdx.x;
    const int wid = tid >> 5, lane = tid & 31;
    const int gid = lane >> 2, tig = lane & 3;
    const int wm = wid & 3, wn = wid >> 2;
    const int m0 = blockIdx.y * 128, n0 = blockIdx.x * 64;

    const uint32_t asBase = (uint32_t)__cvta_generic_to_shared(&As[0][0]);
    const uint32_t bsBase = (uint32_t)__cvta_generic_to_shared(&Bs[0][0]);
    const int lquad = lane >> 3, l7 = lane & 7, l15 = lane & 15;
    const uint32_t aLane = (uint32_t)((((lquad & 1) * 8 + l7) * 80) + (lquad >> 1) * 16);

    float acc[2][4][4] = {};
    const int nkt = K3 >> 5;

    auto ldglobal = [&](int kt, int buf) {
#pragma unroll
        for (int i = 0; i < 2; i++) {
            int u4 = tid + i * 256;
            int row = u4 >> 2, c4 = u4 & 3;
            *(uint4*)&As[buf][row * 40 + c4 * 8] =
                *(const uint4*)&A[(size_t)(m0 + row) * K3 + kt * 32 + c4 * 8];
        }
        {
            int r = tid >> 3, c8 = tid & 7;
            *(uint4*)&Bs[buf][r * 72 + c8 * 8] =
                *(const uint4*)&Bkm[(size_t)(kt * 32 + r) * ldB + n0 + c8 * 8];
        }
    };

    ldglobal(0, 0);
    __syncthreads();
    for (int kt = 0; kt < nkt; kt++) {
        const int buf = kt & 1;
        if (kt + 1 < nkt) ldglobal(kt + 1, buf ^ 1);
#pragma unroll
        for (int ks = 0; ks < 2; ks++) {
            uint32_t a[2][4], b[4][2];
#pragma unroll
            for (int mi = 0; mi < 2; mi++)
                ldsm_x4(a[mi], asBase + (uint32_t)(buf * 128 * 80) +
                               (uint32_t)((wm * 32 + mi * 16) * 80 + ks * 32) + aLane);
#pragma unroll
            for (int ni = 0; ni < 4; ni++)
                ldsm_x2_trans(b[ni], bsBase + (uint32_t)(buf * 32 * 144) +
                              (uint32_t)(((ks * 16 + l15) * 72 + (wn * 32 + ni * 8)) * 2));
#pragma unroll
            for (int mi = 0; mi < 2; mi++)
#pragma unroll
                for (int ni = 0; ni < 4; ni++)
                    mma_bf16(acc[mi][ni], a[mi], b[ni]);
        }
        __syncthreads();
    }

#pragma unroll
    for (int mi = 0; mi < 2; mi++)
#pragma unroll
        for (int ni = 0; ni < 4; ni++) {
            int gm0 = m0 + wm * 32 + mi * 16 + gid;
            int gc0 = n0 + wn * 32 + ni * 8 + tig * 2;
#pragma unroll
            for (int e = 0; e < 4; e++) {
                int gm = gm0 + (e >> 1) * 8;
                int gc = gc0 + (e & 1);
                float v = acc[mi][ni][e];
                if (MODE == 1) {
                    if (gc < Nreal) {
                        int gg = mofs + gm;
                        int bb = gg & 31, tt = gg >> 5;
                        C[(size_t)(bb * T_ + tt) * Nreal + gc] = v + bias[gc];
                    }
                } else {
                    C[(size_t)gm * ldC + gc] = v + bias[gc];
                }
            }
        }
}

// ---------------- fused recurrence step (validated round 3/7) ----------------
template<int BN, int TN, int NKC, int GATE>
__global__ __launch_bounds__(128) void step_gemm(
    const float* __restrict__ A, const float* __restrict__ Bm,
    const float* __restrict__ xb, const float* __restrict__ hb,
    const float* __restrict__ hin, float* __restrict__ hout,
    float* __restrict__ extra, float* __restrict__ part,
    float* __restrict__ qout, unsigned int* __restrict__ ctr,
    int N, int K, int sidx)
{
    __shared__ float As[16][32];
    __shared__ float Bs[16][BN];
    __shared__ int doneflag;
    const int tid = threadIdx.x;
    const int tx = tid & 15, ty = tid >> 4;
    const int n0 = blockIdx.x * BN;
    const int z = blockIdx.z;
    const int k0 = z * NKC * 16;

    float acc[4][TN];
#pragma unroll
    for (int i = 0; i < 4; i++)
#pragma unroll
        for (int j = 0; j < TN; j++) acc[i][j] = 0.f;

    for (int kt = 0; kt < NKC; kt++) {
#pragma unroll
        for (int ii = tid; ii < 512; ii += 128) {
            int k = ii & 15, m = ii >> 4;
            As[k][m] = A[(size_t)m * K + k0 + kt * 16 + k];
        }
        for (int ii = tid; ii < 16 * BN; ii += 128) {
            int k = ii / BN, n = ii - k * BN;
            Bs[k][n] = Bm[(size_t)(k0 + kt * 16 + k) * N + n0 + n];
        }
        __syncthreads();
#pragma unroll
        for (int kk = 0; kk < 16; kk++) {
            float4 av = *reinterpret_cast<const float4*>(&As[kk][ty * 4]);
            float a[4] = {av.x, av.y, av.z, av.w};
#pragma unroll
            for (int j = 0; j < TN; j++) {
                float bv = Bs[kk][tx * TN + j];
#pragma unroll
                for (int i = 0; i < 4; i++) acc[i][j] += a[i] * bv;
            }
        }
        __syncthreads();
    }
#pragma unroll
    for (int i = 0; i < 4; i++) {
        int gm = ty * 4 + i;
#pragma unroll
        for (int j = 0; j < TN; j++)
            part[((size_t)(z * 32 + gm)) * N + n0 + tx * TN + j] = acc[i][j];
    }
    __threadfence();
    __syncthreads();
    if (tid == 0) {
        unsigned int prev = atomicAdd(&ctr[blockIdx.x], 1u);
        doneflag = (prev == 7u);
        if (prev == 7u) ctr[blockIdx.x] = 0u;
    }
    __syncthreads();
    if (!doneflag) return;
    __threadfence();

    if (GATE == 0) {
#pragma unroll
        for (int i = 0; i < 16; i++) {
            int idx = tid + i * 128;
            int b = idx & 31, nl = idx >> 5;
            int n = n0 + nl;
            float s = 0.f;
#pragma unroll
            for (int zz = 0; zz < 8; zz++) s += part[((size_t)(zz * 32 + b)) * N + n];
            qout[b * U_ + n] = s + hb[n];
        }
    } else {
        const int u0 = n0 / 3;
#pragma unroll
        for (int i = 0; i < 4; i++) {
            int idx = tid + i * 128;
            int b = idx & 31, ul = idx >> 5;
            int u = u0 + ul;
            float g[3];
#pragma unroll
            for (int gg = 0; gg < 3; gg++) {
                float s = 0.f;
#pragma unroll
                for (int zz = 0; zz < 8; zz++)
                    s += part[((size_t)(zz * 32 + b)) * N + n0 + ul * 3 + gg];
                g[gg] = s;
            }
            float h;
            if (GATE == 1) {
                const float* gx = xb + (size_t)b * G_;
                float zg = sigm(gx[u] + g[0] + hb[u]);
                float rg = sigm(gx[U_ + u] + g[1] + hb[U_ + u]);
                float cg = tanhf(gx[2 * U_ + u] + rg * (g[2] + hb[2 * U_ + u]));
                h = zg * hin[b * U_ + u] + (1.f - zg) * cg;
                hout[b * U_ + u] = h;
                extra[(size_t)b * (S_ * U_) + u] = h;
                __nv_bfloat16 hi = __float2bfloat16(h);
                __nv_bfloat16 lo = __float2bfloat16(h - __bfloat162float(hi));
                size_t ar = ((size_t)b * 64 + sidx) * 3072;
                d_encS[ar + u] = hi; d_encS[ar + 1024 + u] = lo; d_encS[ar + 2048 + u] = hi;
            } else {
                float zg = sigm(g[0] + xb[u] + hb[u]);
                float rg = sigm(g[1] + xb[U_ + u] + hb[U_ + u]);
                float cg = tanhf(g[2] + xb[2 * U_ + u] + rg * hb[2 * U_ + u]);
                h = (1.f - zg) * cg;
                hout[b * U_ + u] = h;
                extra[(size_t)b * U_ + u] = h;
                __nv_bfloat16 hi = __float2bfloat16(h);
                __nv_bfloat16 lo = __float2bfloat16(h - __bfloat162float(hi));
                size_t ar = ((size_t)sidx * 32 + b) * 3072;
                d_HallS[ar + u] = hi; d_HallS[ar + 1024 + u] = lo; d_HallS[ar + 2048 + u] = hi;
            }
        }
    }
}

// ---------------- attention + context (512 threads, warp softmax) ----------------
__global__ void attn_ctx(const float* __restrict__ Va, const float* __restrict__ bvp,
                         const float* __restrict__ Ed, const int* __restrict__ teacher, int t)
{
    const int b = blockIdx.x, tid = threadIdx.x;
    __shared__ float qs[U_];
    __shared__ float sc[S_];

    for (int u = tid; u < U_; u += 512) qs[u] = d_q[b * U_ + u];
    __syncthreads();

    const int w = tid >> 5, lane = tid & 31;
    for (int s = w; s < S_; s += 16) {
        const float* pr = d_pre + (size_t)b * (S_ * U_) + (size_t)s * U_;
        float p = 0.f;
        for (int u = lane; u < U_; u += 32) p += tanhf(pr[u] + qs[u]) * Va[u];
#pragma unroll
        for (int o = 16; o > 0; o >>= 1) p += __shfl_xor_sync(0xffffffffu, p, o);
        if (lane == 0) sc[s] = p + bvp[0];
    }
    __syncthreads();

    if (tid < 32) {
        float v0 = sc[tid], v1 = sc[tid + 32];
        float m = fmaxf(v0, v1);
#pragma unroll
        for (int o = 16; o > 0; o >>= 1) m = fmaxf(m, __shfl_xor_sync(0xffffffffu, m, o));
        float e0 = expf(v0 - m), e1 = expf(v1 - m);
        float s = e0 + e1;
#pragma unroll
        for (int o = 16; o > 0; o >>= 1) s += __shfl_xor_sync(0xffffffffu, s, o);
        float inv = 1.f / s;
        sc[tid] = e0 * inv; sc[tid + 32] = e1 * inv;
    }
    __syncthreads();

    for (int u = tid; u < U_; u += 512) {
        float a = 0.f;
        const float* eb = d_enc + (size_t)b * (S_ * U_) + u;
#pragma unroll 8
        for (int s = 0; s < S_; s++) a += sc[s] * eb[(size_t)s * U_];
        d_xcat[(size_t)b * (U_ + E_) + u] = a;
    }
    const int tok = teacher[b * T_ + t];
    if (tid < E_) d_xcat[(size_t)b * (U_ + E_) + U_ + tid] = Ed[(size_t)tok * E_ + tid];
}

// ---------------- argmax ----------------
__global__ void argmax_k(const float* __restrict__ logits, long long* outI, float* outF, int asFloat)
{
    const int row = blockIdx.x;
    const float* p = logits + (size_t)row * V_;
    const int tid = threadIdx.x;
    float best = -INFINITY; int bi = 0;
    for (int v = tid; v < V_; v += 256) {
        float val = p[v];
        if (val > best) { best = val; bi = v; }
    }
    __shared__ float bvs[256]; __shared__ int bis[256];
    bvs[tid] = best; bis[tid] = bi;
    __syncthreads();
    for (int st = 128; st > 0; st >>= 1) {
        if (tid < st) {
            float ov = bvs[tid + st]; int oi = bis[tid + st];
            if (ov > bvs[tid] || (ov == bvs[tid] && oi < bis[tid])) { bvs[tid] = ov; bis[tid] = oi; }
        }
        __syncthreads();
    }
    if (tid == 0) {
        if (asFloat) outF[row] = (float)bis[0];
        else         outI[row] = (long long)bis[0];
    }
}

// ---------------- launcher ----------------
static float* symaddr(const void* sym) {
    void* p = nullptr;
    cudaGetSymbolAddress(&p, sym);
    return (float*)p;
}

extern "C" void kernel_launch(void* const* d_in, const int* in_sizes, int n_in,
                              void* d_out, int out_size)
{
    static cudaStream_t s2 = nullptr;
    static cudaEvent_t ev[10];
    if (!s2) {
        cudaStreamCreateWithFlags(&s2, cudaStreamNonBlocking);
        for (int i = 0; i < 10; i++) cudaEventCreateWithFlags(&ev[i], cudaEventDisableTiming);
    }

    const int s0 = (n_in >= 22) ? 4 : 2;
    const int*   enc_in  = (const int*)d_in[0];
    const int*   teacher = (const int*)d_in[1];
    const float* Ee      = (const float*)d_in[s0 + 0];
    const float* eWx     = (const float*)d_in[s0 + 1];
    const float* eWh     = (const float*)d_in[s0 + 2];
    const float* eb_in   = (const float*)d_in[s0 + 3];
    const float* eb_rec  = (const float*)d_in[s0 + 4];
    const float* Ed      = (const float*)d_in[s0 + 5];
    const float* dWx     = (const float*)d_in[s0 + 6];
    const float* db_in   = (const float*)d_in[s0 + 8];
    const float* db_rec  = (const float*)d_in[s0 + 9];
    const float* W1      = (const float*)d_in[s0 + 10];
    const float* b1      = (const float*)d_in[s0 + 11];
    const float* W2      = (const float*)d_in[s0 + 12];
    const float* b2      = (const float*)d_in[s0 + 13];
    const float* Va      = (const float*)d_in[s0 + 14];
    const float* bvp     = (const float*)d_in[s0 + 15];
    const float* Wf      = (const float*)d_in[s0 + 16];
    const float* bf      = (const float*)d_in[s0 + 17];

    float* hbase = symaddr(d_hbuf);
    float* hdec  = symaddr(d_hdec);
    float* encp  = symaddr(d_enc);
    float* prep  = symaddr(d_pre);
    float* qp    = symaddr(d_q);
    float* gpart = symaddr(d_gpart);
    float* xcat  = symaddr(d_xcat);
    float* Hall  = symaddr(d_Hall);
    float* lalt  = symaddr(d_logits_alt);
    float* gxall = symaddr(d_gxall);
    float* WhP   = symaddr(d_WhP);
    float* dWxP  = symaddr(d_dWxP);
    unsigned int* ctr; { void* p; cudaGetSymbolAddress(&p, d_ctr); ctr = (unsigned int*)p; }
    __nv_bfloat16* WfT3;  { void* p; cudaGetSymbolAddress(&p, d_WfT3);  WfT3  = (__nv_bfloat16*)p; }
    __nv_bfloat16* W1T3;  { void* p; cudaGetSymbolAddress(&p, d_W1T3);  W1T3  = (__nv_bfloat16*)p; }
    __nv_bfloat16* eWxT3; { void* p; cudaGetSymbolAddress(&p, d_eWxT3); eWxT3 = (__nv_bfloat16*)p; }
    __nv_bfloat16* xembS; { void* p; cudaGetSymbolAddress(&p, d_xembS); xembS = (__nv_bfloat16*)p; }
    __nv_bfloat16* encS;  { void* p; cudaGetSymbolAddress(&p, d_encS);  encS  = (__nv_bfloat16*)p; }
    __nv_bfloat16* HallS; { void* p; cudaGetSymbolAddress(&p, d_HallS); HallS = (__nv_bfloat16*)p; }

    const long long LOGN = (long long)B_ * T_ * V_;
    float* logits_dst = (float*)d_out;
    long long* predI = nullptr; float* predF = nullptr; int asFloat = 0;
    if ((long long)out_size == LOGN + 512) { predF = (float*)d_out + LOGN; asFloat = 1; }
    else if ((long long)out_size == LOGN + 1024) { predI = (long long*)((float*)d_out + LOGN); }
    else if (out_size == 512) { logits_dst = lalt; predI = (long long*)d_out; }

    cudaMemsetAsync(hbase, 0, (size_t)B_ * U_ * sizeof(float));

    // fork side stream: W1 split, dWx permute, Wf split (in that order), overlapping encoder
    cudaEventRecord(ev[0], 0);
    cudaStreamWaitEvent(s2, ev[0], 0);
    conv_splitB_v8<<<(U_ * (U_ / 8) + 255) / 256, 256, 0, s2>>>(W1, W1T3, U_, U_, U_);
    cudaEventRecord(ev[1], s2);                     // W1 ready
    perm3<<<(U_ + E_) * G_ / 256, 256, 0, s2>>>(dWx, dWxP);
    cudaEventRecord(ev[2], s2);                     // dWxP ready
    conv_splitB_v8<<<(U_ * (VP_ / 8) + 255) / 256, 256, 0, s2>>>(Wf, WfT3, U_, V_, VP_);

    // main stream: encoder front
    perm3<<<U_ * G_ / 256, 256>>>(eWh, WhP);
    conv_splitB_v8<<<(E_ * (G_ / 8) + 255) / 256, 256>>>(eWx, eWxT3, E_, G_, G_);
    embed_split<<<2048, 256>>>(enc_in, Ee);
    gemm_bf16<0><<<dim3(G_ / 64, (S_ * B_) / 128), 256>>>(xembS, eWxT3, eb_in, gxall, G_, G_, 768, G_, 0);

    // encoder recurrence
    for (int s = 0; s < S_; s++) {
        float* hin  = hbase + (size_t)(s & 1) * B_ * U_;
        float* hout = hbase + (size_t)((s + 1) & 1) * B_ * U_;
        step_gemm<48,3,8,1><<<dim3(G_ / 48, 1, 8), 128>>>(
            hin, WhP, gxall + (size_t)s * B_ * G_, eb_rec,
            hin, hout, encp + (size_t)s * U_, gpart, nullptr, ctr, G_, U_, s);
    }

    // pre_enc (needs W1T3 from s2)
    cudaStreamWaitEvent(0, ev[1], 0);
    gemm_bf16<0><<<dim3(U_ / 64, (B_ * S_) / 128), 256>>>(encS, W1T3, b1, prep, U_, U_, 3072, U_, 0);

    // decoder (needs dWxP from s2)
    cudaStreamWaitEvent(0, ev[2], 0);
    for (int t = 0; t < T_; t++) {
        const float* hd = (t == 0) ? hbase : hdec;
        step_gemm<64,4,8,0><<<dim3(U_ / 64, 1, 8), 128>>>(
            hd, W2, nullptr, b2, nullptr, nullptr, nullptr, gpart, qp, ctr + 64, U_, U_, t);
        attn_ctx<<<B_, 512>>>(Va, bvp, Ed, teacher, t);
        step_gemm<48,3,10,2><<<dim3(G_ / 48, 1, 8), 128>>>(
            xcat, dWxP, db_in, db_rec, nullptr, hdec,
            Hall + (size_t)t * B_ * U_, gpart, nullptr, ctr + 128, G_, U_ + E_, t);
        // logits chunk for rows [c*128, c*128+128) once steps 4c..4c+3 are done
        if ((t & 3) == 3) {
            int c = t >> 2;
            cudaEventRecord(ev[3 + c], 0);
            cudaStreamWaitEvent(s2, ev[3 + c], 0);
            gemm_bf16<1><<<dim3(VP_ / 64, 1), 256, 0, s2>>>(
                HallS + (size_t)c * 128 * 3072, WfT3, bf, logits_dst, 0, V_, 3072, VP_, c * 128);
        }
    }

    // join side stream, then argmax
    cudaEventRecord(ev[7], s2);
    cudaStreamWaitEvent(0, ev[7], 0);
    if (predI || predF) argmax_k<<<T_ * B_, 256>>>(logits_dst, predI, predF, asFloat);
}

// round 10
// speedup vs baseline: 1.7221x; 1.1137x over previous
#include <cuda_runtime.h>
#include <cuda_bf16.h>
#include <math.h>
#include <stdint.h>

#define B_ 32
#define S_ 64
#define T_ 16
#define U_ 1024
#define E_ 256
#define V_ 20200
#define G_ 3072
#define VP_ 20224

// ---------------- device scratch ----------------
__device__ __align__(16) float d_gxall[S_*B_*G_];
__device__ __align__(16) float d_hbuf[2][B_*U_];
__device__ __align__(16) float d_hdec[B_*U_];
__device__ __align__(16) float d_enc[B_*S_*U_];          // [b][s][u] == rows b*64+s
__device__ __align__(16) float d_pre[B_*S_*U_];          // rows b*64+s
__device__ __align__(16) float d_q[B_*U_];
__device__ __align__(16) float d_gpart[8][B_*G_];
__device__ __align__(16) float d_xcat[B_*(U_+E_)];
__device__ __align__(16) float d_Hall[T_*B_*U_];         // rows t*32+b
__device__ __align__(16) float d_logits_alt[T_*B_*V_];
__device__ __align__(16) float d_WhP[U_*G_];
__device__ __align__(16) float d_dWxP[(U_+E_)*G_];
__device__ __align__(16) __nv_bfloat16 d_WfT3[(size_t)3*1024*VP_];
__device__ __align__(16) __nv_bfloat16 d_W1T3[3*1024*1024];
__device__ __align__(16) __nv_bfloat16 d_eWxT3[3*256*G_];
__device__ __align__(16) __nv_bfloat16 d_xembS[2048*768];
__device__ __align__(16) __nv_bfloat16 d_encS[(size_t)2048*3072];   // rows b*64+s
__device__ __align__(16) __nv_bfloat16 d_HallS[512*3072];           // rows t*32+b
__device__ unsigned int d_ctr[3*64];

__device__ __forceinline__ float sigm(float x) { return 1.f / (1.f + expf(-x)); }

// ---------------- setup kernels ----------------
__global__ void perm3(const float* __restrict__ W, float* __restrict__ out) {
    int idx = blockIdx.x * 256 + threadIdx.x;
    int k = idx / G_, c = idx - k * G_;
    int u = c / 3, g = c - u * 3;
    out[idx] = W[(size_t)k * G_ + g * U_ + u];
}

__global__ void embed_split(const int* __restrict__ enc_in, const float* __restrict__ Ee) {
    int idx = blockIdx.x * 256 + threadIdx.x;
    int r = idx >> 8, e = idx & 255;
    int s = r >> 5, b = r & 31;
    float x = Ee[(size_t)enc_in[b * S_ + s] * E_ + e];
    __nv_bfloat16 hi = __float2bfloat16(x);
    __nv_bfloat16 lo = __float2bfloat16(x - __bfloat162float(hi));
    size_t base = (size_t)r * 768;
    d_xembS[base + e] = hi; d_xembS[base + 256 + e] = lo; d_xembS[base + 512 + e] = hi;
}

// A [M][1024] fp32 -> [M][3072] bf16 = [hi|lo|hi]
__global__ void conv_splitA(const float* __restrict__ A, __nv_bfloat16* __restrict__ out) {
    int idx = blockIdx.x * 256 + threadIdx.x;
    int m = idx >> 10, k = idx & 1023;
    float x = A[idx];
    __nv_bfloat16 hi = __float2bfloat16(x);
    __nv_bfloat16 lo = __float2bfloat16(x - __bfloat162float(hi));
    size_t base = (size_t)m * 3072;
    out[base + k] = hi; out[base + 1024 + k] = lo; out[base + 2048 + k] = hi;
}

__global__ void conv_splitB_v8(const float* __restrict__ W, __nv_bfloat16* __restrict__ out,
                               int K, int N, int NP) {
    int idx = blockIdx.x * 256 + threadIdx.x;
    int per = NP >> 3;
    int k = idx / per, n = (idx - k * per) * 8;
    if (k >= K) return;
    float v[8];
    if (n + 8 <= N) {
        float4 a = *(const float4*)&W[(size_t)k * N + n];
        float4 b = *(const float4*)&W[(size_t)k * N + n + 4];
        v[0]=a.x; v[1]=a.y; v[2]=a.z; v[3]=a.w; v[4]=b.x; v[5]=b.y; v[6]=b.z; v[7]=b.w;
    } else {
#pragma unroll
        for (int j = 0; j < 8; j++) v[j] = (n + j < N) ? W[(size_t)k * N + n + j] : 0.f;
    }
    __nv_bfloat16 hi[8], lo[8];
#pragma unroll
    for (int j = 0; j < 8; j++) {
        hi[j] = __float2bfloat16(v[j]);
        lo[j] = __float2bfloat16(v[j] - __bfloat162float(hi[j]));
    }
    size_t p = (size_t)k * NP + n, sK = (size_t)K * NP;
    *(uint4*)&out[p]          = *(uint4*)hi;
    *(uint4*)&out[sK + p]     = *(uint4*)hi;
    *(uint4*)&out[2 * sK + p] = *(uint4*)lo;
}

// ---------------- tensor-core bf16 GEMM ----------------
__device__ __forceinline__ void mma_bf16(float* c, const uint32_t* a, const uint32_t* b) {
    asm volatile("mma.sync.aligned.m16n8k16.row.col.f32.bf16.bf16.f32 "
        "{%0,%1,%2,%3},{%4,%5,%6,%7},{%8,%9},{%0,%1,%2,%3};"
        : "+f"(c[0]), "+f"(c[1]), "+f"(c[2]), "+f"(c[3])
        : "r"(a[0]), "r"(a[1]), "r"(a[2]), "r"(a[3]), "r"(b[0]), "r"(b[1]));
}
__device__ __forceinline__ void ldsm_x4(uint32_t* r, uint32_t addr) {
    asm volatile("ldmatrix.sync.aligned.m8n8.x4.shared.b16 {%0,%1,%2,%3}, [%4];"
        : "=r"(r[0]), "=r"(r[1]), "=r"(r[2]), "=r"(r[3]) : "r"(addr));
}
__device__ __forceinline__ void ldsm_x2_trans(uint32_t* r, uint32_t addr) {
    asm volatile("ldmatrix.sync.aligned.m8n8.x2.trans.shared.b16 {%0,%1}, [%2];"
        : "=r"(r[0]), "=r"(r[1]) : "r"(addr));
}

// MODE 0: C[gm*ldC+gc]; MODE 1: logits scatter, global row = mofs+gm = t*32+b -> row b*16+t
template<int MODE>
__global__ __launch_bounds__(256) void gemm_bf16(
    const __nv_bfloat16* __restrict__ A, const __nv_bfloat16* __restrict__ Bkm,
    const float* __restrict__ bias, float* __restrict__ C,
    int ldC, int Nreal, int K3, int ldB, int mofs)
{
    __shared__ __nv_bfloat16 As[2][128 * 40];
    __shared__ __nv_bfloat16 Bs[2][32 * 72];
    const int tid = threadIdx.x;
    const int wid = tid >> 5, lane = tid & 31;
    const int gid = lane >> 2, tig = lane & 3;
    const int wm = wid & 3, wn = wid >> 2;
    const int m0 = blockIdx.y * 128, n0 = blockIdx.x * 64;

    const uint32_t asBase = (uint32_t)__cvta_generic_to_shared(&As[0][0]);
    const uint32_t bsBase = (uint32_t)__cvta_generic_to_shared(&Bs[0][0]);
    const int lquad = lane >> 3, l7 = lane & 7, l15 = lane & 15;
    const uint32_t aLane = (uint32_t)((((lquad & 1) * 8 + l7) * 80) + (lquad >> 1) * 16);

    float acc[2][4][4] = {};
    const int nkt = K3 >> 5;

    auto ldglobal = [&](int kt, int buf) {
#pragma unroll
        for (int i = 0; i < 2; i++) {
            int u4 = tid + i * 256;
            int row = u4 >> 2, c4 = u4 & 3;
            *(uint4*)&As[buf][row * 40 + c4 * 8] =
                *(const uint4*)&A[(size_t)(m0 + row) * K3 + kt * 32 + c4 * 8];
        }
        {
            int r = tid >> 3, c8 = tid & 7;
            *(uint4*)&Bs[buf][r * 72 + c8 * 8] =
                *(const uint4*)&Bkm[(size_t)(kt * 32 + r) * ldB + n0 + c8 * 8];
        }
    };

    ldglobal(0, 0);
    __syncthreads();
    for (int kt = 0; kt < nkt; kt++) {
        const int buf = kt & 1;
        if (kt + 1 < nkt) ldglobal(kt + 1, buf ^ 1);
#pragma unroll
        for (int ks = 0; ks < 2; ks++) {
            uint32_t a[2][4], b[4][2];
#pragma unroll
            for (int mi = 0; mi < 2; mi++)
                ldsm_x4(a[mi], asBase + (uint32_t)(buf * 128 * 80) +
                               (uint32_t)((wm * 32 + mi * 16) * 80 + ks * 32) + aLane);
#pragma unroll
            for (int ni = 0; ni < 4; ni++)
                ldsm_x2_trans(b[ni], bsBase + (uint32_t)(buf * 32 * 144) +
                              (uint32_t)(((ks * 16 + l15) * 72 + (wn * 32 + ni * 8)) * 2));
#pragma unroll
            for (int mi = 0; mi < 2; mi++)
#pragma unroll
                for (int ni = 0; ni < 4; ni++)
                    mma_bf16(acc[mi][ni], a[mi], b[ni]);
        }
        __syncthreads();
    }

#pragma unroll
    for (int mi = 0; mi < 2; mi++)
#pragma unroll
        for (int ni = 0; ni < 4; ni++) {
            int gm0 = m0 + wm * 32 + mi * 16 + gid;
            int gc0 = n0 + wn * 32 + ni * 8 + tig * 2;
#pragma unroll
            for (int e = 0; e < 4; e++) {
                int gm = gm0 + (e >> 1) * 8;
                int gc = gc0 + (e & 1);
                float v = acc[mi][ni][e];
                if (MODE == 1) {
                    if (gc < Nreal) {
                        int gg = mofs + gm;
                        int bb = gg & 31, tt = gg >> 5;
                        C[(size_t)(bb * T_ + tt) * Nreal + gc] = v + bias[gc];
                    }
                } else {
                    C[(size_t)gm * ldC + gc] = v + bias[gc];
                }
            }
        }
}

// ---------------- fused recurrence step (round-3 gates: NO archive writes) --------
template<int BN, int TN, int NKC, int GATE>
__global__ __launch_bounds__(128) void step_gemm(
    const float* __restrict__ A, const float* __restrict__ Bm,
    const float* __restrict__ xb, const float* __restrict__ hb,
    const float* __restrict__ hin, float* __restrict__ hout,
    float* __restrict__ extra, float* __restrict__ part,
    float* __restrict__ qout, unsigned int* __restrict__ ctr,
    int N, int K)
{
    __shared__ float As[16][32];
    __shared__ float Bs[16][BN];
    __shared__ int doneflag;
    const int tid = threadIdx.x;
    const int tx = tid & 15, ty = tid >> 4;
    const int n0 = blockIdx.x * BN;
    const int z = blockIdx.z;
    const int k0 = z * NKC * 16;

    float acc[4][TN];
#pragma unroll
    for (int i = 0; i < 4; i++)
#pragma unroll
        for (int j = 0; j < TN; j++) acc[i][j] = 0.f;

    for (int kt = 0; kt < NKC; kt++) {
#pragma unroll
        for (int ii = tid; ii < 512; ii += 128) {
            int k = ii & 15, m = ii >> 4;
            As[k][m] = A[(size_t)m * K + k0 + kt * 16 + k];
        }
        for (int ii = tid; ii < 16 * BN; ii += 128) {
            int k = ii / BN, n = ii - k * BN;
            Bs[k][n] = Bm[(size_t)(k0 + kt * 16 + k) * N + n0 + n];
        }
        __syncthreads();
#pragma unroll
        for (int kk = 0; kk < 16; kk++) {
            float4 av = *reinterpret_cast<const float4*>(&As[kk][ty * 4]);
            float a[4] = {av.x, av.y, av.z, av.w};
#pragma unroll
            for (int j = 0; j < TN; j++) {
                float bv = Bs[kk][tx * TN + j];
#pragma unroll
                for (int i = 0; i < 4; i++) acc[i][j] += a[i] * bv;
            }
        }
        __syncthreads();
    }
#pragma unroll
    for (int i = 0; i < 4; i++) {
        int gm = ty * 4 + i;
#pragma unroll
        for (int j = 0; j < TN; j++)
            part[((size_t)(z * 32 + gm)) * N + n0 + tx * TN + j] = acc[i][j];
    }
    __threadfence();
    __syncthreads();
    if (tid == 0) {
        unsigned int prev = atomicAdd(&ctr[blockIdx.x], 1u);
        doneflag = (prev == 7u);
        if (prev == 7u) ctr[blockIdx.x] = 0u;
    }
    __syncthreads();
    if (!doneflag) return;
    __threadfence();

    if (GATE == 0) {
#pragma unroll
        for (int i = 0; i < 16; i++) {
            int idx = tid + i * 128;
            int b = idx & 31, nl = idx >> 5;
            int n = n0 + nl;
            float s = 0.f;
#pragma unroll
            for (int zz = 0; zz < 8; zz++) s += part[((size_t)(zz * 32 + b)) * N + n];
            qout[b * U_ + n] = s + hb[n];
        }
    } else {
        const int u0 = n0 / 3;
#pragma unroll
        for (int i = 0; i < 4; i++) {
            int idx = tid + i * 128;
            int b = idx & 31, ul = idx >> 5;
            int u = u0 + ul;
            float g[3];
#pragma unroll
            for (int gg = 0; gg < 3; gg++) {
                float s = 0.f;
#pragma unroll
                for (int zz = 0; zz < 8; zz++)
                    s += part[((size_t)(zz * 32 + b)) * N + n0 + ul * 3 + gg];
                g[gg] = s;
            }
            float h;
            if (GATE == 1) {
                const float* gx = xb + (size_t)b * G_;
                float zg = sigm(gx[u] + g[0] + hb[u]);
                float rg = sigm(gx[U_ + u] + g[1] + hb[U_ + u]);
                float cg = tanhf(gx[2 * U_ + u] + rg * (g[2] + hb[2 * U_ + u]));
                h = zg * hin[b * U_ + u] + (1.f - zg) * cg;
                hout[b * U_ + u] = h;
                extra[(size_t)b * (S_ * U_) + u] = h;       // d_enc + s*U_
            } else {
                float zg = sigm(g[0] + xb[u] + hb[u]);
                float rg = sigm(g[1] + xb[U_ + u] + hb[U_ + u]);
                float cg = tanhf(g[2] + xb[2 * U_ + u] + rg * hb[2 * U_ + u]);
                h = (1.f - zg) * cg;
                hout[b * U_ + u] = h;                        // d_hdec
                extra[(size_t)b * U_ + u] = h;               // d_Hall + t*B*U
            }
        }
    }
}

// ---------------- attention + context (512 threads, warp softmax) ----------------
__global__ void attn_ctx(const float* __restrict__ Va, const float* __restrict__ bvp,
                         const float* __restrict__ Ed, const int* __restrict__ teacher, int t)
{
    const int b = blockIdx.x, tid = threadIdx.x;
    __shared__ float qs[U_];
    __shared__ float sc[S_];

    for (int u = tid; u < U_; u += 512) qs[u] = d_q[b * U_ + u];
    __syncthreads();

    const int w = tid >> 5, lane = tid & 31;
    for (int s = w; s < S_; s += 16) {
        const float* pr = d_pre + (size_t)b * (S_ * U_) + (size_t)s * U_;
        float p = 0.f;
        for (int u = lane; u < U_; u += 32) p += tanhf(pr[u] + qs[u]) * Va[u];
#pragma unroll
        for (int o = 16; o > 0; o >>= 1) p += __shfl_xor_sync(0xffffffffu, p, o);
        if (lane == 0) sc[s] = p + bvp[0];
    }
    __syncthreads();

    if (tid < 32) {
        float v0 = sc[tid], v1 = sc[tid + 32];
        float m = fmaxf(v0, v1);
#pragma unroll
        for (int o = 16; o > 0; o >>= 1) m = fmaxf(m, __shfl_xor_sync(0xffffffffu, m, o));
        float e0 = expf(v0 - m), e1 = expf(v1 - m);
        float s = e0 + e1;
#pragma unroll
        for (int o = 16; o > 0; o >>= 1) s += __shfl_xor_sync(0xffffffffu, s, o);
        float inv = 1.f / s;
        sc[tid] = e0 * inv; sc[tid + 32] = e1 * inv;
    }
    __syncthreads();

    for (int u = tid; u < U_; u += 512) {
        float a = 0.f;
        const float* eb = d_enc + (size_t)b * (S_ * U_) + u;
#pragma unroll 8
        for (int s = 0; s < S_; s++) a += sc[s] * eb[(size_t)s * U_];
        d_xcat[(size_t)b * (U_ + E_) + u] = a;
    }
    const int tok = teacher[b * T_ + t];
    if (tid < E_) d_xcat[(size_t)b * (U_ + E_) + U_ + tid] = Ed[(size_t)tok * E_ + tid];
}

// ---------------- argmax ----------------
__global__ void argmax_k(const float* __restrict__ logits, long long* outI, float* outF, int asFloat)
{
    const int row = blockIdx.x;
    const float* p = logits + (size_t)row * V_;
    const int tid = threadIdx.x;
    float best = -INFINITY; int bi = 0;
    for (int v = tid; v < V_; v += 256) {
        float val = p[v];
        if (val > best) { best = val; bi = v; }
    }
    __shared__ float bvs[256]; __shared__ int bis[256];
    bvs[tid] = best; bis[tid] = bi;
    __syncthreads();
    for (int st = 128; st > 0; st >>= 1) {
        if (tid < st) {
            float ov = bvs[tid + st]; int oi = bis[tid + st];
            if (ov > bvs[tid] || (ov == bvs[tid] && oi < bis[tid])) { bvs[tid] = ov; bis[tid] = oi; }
        }
        __syncthreads();
    }
    if (tid == 0) {
        if (asFloat) outF[row] = (float)bis[0];
        else         outI[row] = (long long)bis[0];
    }
}

// ---------------- launcher ----------------
static float* symaddr(const void* sym) {
    void* p = nullptr;
    cudaGetSymbolAddress(&p, sym);
    return (float*)p;
}

extern "C" void kernel_launch(void* const* d_in, const int* in_sizes, int n_in,
                              void* d_out, int out_size)
{
    static cudaStream_t s2 = nullptr;
    static cudaEvent_t ev[10];
    if (!s2) {
        cudaStreamCreateWithFlags(&s2, cudaStreamNonBlocking);
        for (int i = 0; i < 10; i++) cudaEventCreateWithFlags(&ev[i], cudaEventDisableTiming);
    }

    const int s0 = (n_in >= 22) ? 4 : 2;
    const int*   enc_in  = (const int*)d_in[0];
    const int*   teacher = (const int*)d_in[1];
    const float* Ee      = (const float*)d_in[s0 + 0];
    const float* eWx     = (const float*)d_in[s0 + 1];
    const float* eWh     = (const float*)d_in[s0 + 2];
    const float* eb_in   = (const float*)d_in[s0 + 3];
    const float* eb_rec  = (const float*)d_in[s0 + 4];
    const float* Ed      = (const float*)d_in[s0 + 5];
    const float* dWx     = (const float*)d_in[s0 + 6];
    const float* db_in   = (const float*)d_in[s0 + 8];
    const float* db_rec  = (const float*)d_in[s0 + 9];
    const float* W1      = (const float*)d_in[s0 + 10];
    const float* b1      = (const float*)d_in[s0 + 11];
    const float* W2      = (const float*)d_in[s0 + 12];
    const float* b2      = (const float*)d_in[s0 + 13];
    const float* Va      = (const float*)d_in[s0 + 14];
    const float* bvp     = (const float*)d_in[s0 + 15];
    const float* Wf      = (const float*)d_in[s0 + 16];
    const float* bf      = (const float*)d_in[s0 + 17];

    float* hbase = symaddr(d_hbuf);
    float* hdec  = symaddr(d_hdec);
    float* encp  = symaddr(d_enc);
    float* prep  = symaddr(d_pre);
    float* qp    = symaddr(d_q);
    float* gpart = symaddr(d_gpart);
    float* xcat  = symaddr(d_xcat);
    float* Hall  = symaddr(d_Hall);
    float* lalt  = symaddr(d_logits_alt);
    float* gxall = symaddr(d_gxall);
    float* WhP   = symaddr(d_WhP);
    float* dWxP  = symaddr(d_dWxP);
    unsigned int* ctr; { void* p; cudaGetSymbolAddress(&p, d_ctr); ctr = (unsigned int*)p; }
    __nv_bfloat16* WfT3;  { void* p; cudaGetSymbolAddress(&p, d_WfT3);  WfT3  = (__nv_bfloat16*)p; }
    __nv_bfloat16* W1T3;  { void* p; cudaGetSymbolAddress(&p, d_W1T3);  W1T3  = (__nv_bfloat16*)p; }
    __nv_bfloat16* eWxT3; { void* p; cudaGetSymbolAddress(&p, d_eWxT3); eWxT3 = (__nv_bfloat16*)p; }
    __nv_bfloat16* xembS; { void* p; cudaGetSymbolAddress(&p, d_xembS); xembS = (__nv_bfloat16*)p; }
    __nv_bfloat16* encS;  { void* p; cudaGetSymbolAddress(&p, d_encS);  encS  = (__nv_bfloat16*)p; }
    __nv_bfloat16* HallS; { void* p; cudaGetSymbolAddress(&p, d_HallS); HallS = (__nv_bfloat16*)p; }

    const long long LOGN = (long long)B_ * T_ * V_;
    float* logits_dst = (float*)d_out;
    long long* predI = nullptr; float* predF = nullptr; int asFloat = 0;
    if ((long long)out_size == LOGN + 512) { predF = (float*)d_out + LOGN; asFloat = 1; }
    else if ((long long)out_size == LOGN + 1024) { predI = (long long*)((float*)d_out + LOGN); }
    else if (out_size == 512) { logits_dst = lalt; predI = (long long*)d_out; }

    cudaMemsetAsync(hbase, 0, (size_t)B_ * U_ * sizeof(float));

    // fork side stream: W1 split, dWx permute, Wf split — overlapping encoder
    cudaEventRecord(ev[0], 0);
    cudaStreamWaitEvent(s2, ev[0], 0);
    conv_splitB_v8<<<(U_ * (U_ / 8) + 255) / 256, 256, 0, s2>>>(W1, W1T3, U_, U_, U_);
    cudaEventRecord(ev[1], s2);                     // W1T3 ready
    perm3<<<(U_ + E_) * G_ / 256, 256, 0, s2>>>(dWx, dWxP);
    cudaEventRecord(ev[2], s2);                     // dWxP ready
    conv_splitB_v8<<<(U_ * (VP_ / 8) + 255) / 256, 256, 0, s2>>>(Wf, WfT3, U_, V_, VP_);

    // main stream: encoder front
    perm3<<<U_ * G_ / 256, 256>>>(eWh, WhP);
    conv_splitB_v8<<<(E_ * (G_ / 8) + 255) / 256, 256>>>(eWx, eWxT3, E_, G_, G_);
    embed_split<<<2048, 256>>>(enc_in, Ee);
    gemm_bf16<0><<<dim3(G_ / 64, (S_ * B_) / 128), 256>>>(xembS, eWxT3, eb_in, gxall, G_, G_, 768, G_, 0);

    // encoder recurrence (round-3 step kernels)
    for (int s = 0; s < S_; s++) {
        float* hin  = hbase + (size_t)(s & 1) * B_ * U_;
        float* hout = hbase + (size_t)((s + 1) & 1) * B_ * U_;
        step_gemm<48,3,8,1><<<dim3(G_ / 48, 1, 8), 128>>>(
            hin, WhP, gxall + (size_t)s * B_ * G_, eb_rec,
            hin, hout, encp + (size_t)s * U_, gpart, nullptr, ctr, G_, U_);
    }

    // pre_enc: bulk split of d_enc then GEMM (needs W1T3 from s2)
    conv_splitA<<<(B_ * S_ * U_) / 256, 256>>>(encp, encS);
    cudaStreamWaitEvent(0, ev[1], 0);
    gemm_bf16<0><<<dim3(U_ / 64, (B_ * S_) / 128), 256>>>(encS, W1T3, b1, prep, U_, U_, 3072, U_, 0);

    // decoder (needs dWxP from s2)
    cudaStreamWaitEvent(0, ev[2], 0);
    for (int t = 0; t < T_; t++) {
        const float* hd = (t == 0) ? hbase : hdec;
        step_gemm<64,4,8,0><<<dim3(U_ / 64, 1, 8), 128>>>(
            hd, W2, nullptr, b2, nullptr, nullptr, nullptr, gpart, qp, ctr + 64, U_, U_);
        attn_ctx<<<B_, 512>>>(Va, bvp, Ed, teacher, t);
        step_gemm<48,3,10,2><<<dim3(G_ / 48, 1, 8), 128>>>(
            xcat, dWxP, db_in, db_rec, nullptr, hdec,
            Hall + (size_t)t * B_ * U_, gpart, nullptr, ctr + 128, G_, U_ + E_);
        // per-chunk Hall split + logits GEMM on s2 once steps 4c..4c+3 are done
        if ((t & 3) == 3) {
            int c = t >> 2;
            cudaEventRecord(ev[3 + c], 0);
            cudaStreamWaitEvent(s2, ev[3 + c], 0);
            conv_splitA<<<512, 256, 0, s2>>>(Hall + (size_t)c * 128 * U_,
                                             HallS + (size_t)c * 128 * 3072);
            gemm_bf16<1><<<dim3(VP_ / 64, 1), 256, 0, s2>>>(
                HallS + (size_t)c * 128 * 3072, WfT3, bf, logits_dst, 0, V_, 3072, VP_, c * 128);
        }
    }

    // join side stream, then argmax
    cudaEventRecord(ev[7], s2);
    cudaStreamWaitEvent(0, ev[7], 0);
    if (predI || predF) argmax_k<<<T_ * B_, 256>>>(logits_dst, predI, predF, asFloat);
}

// round 11
// speedup vs baseline: 2.1186x; 1.2303x over previous
#include <cuda_runtime.h>
#include <cuda_bf16.h>
#include <math.h>
#include <stdint.h>

#define B_ 32
#define S_ 64
#define T_ 16
#define U_ 1024
#define E_ 256
#define V_ 20200
#define G_ 3072
#define VP_ 20224

// ---------------- device scratch ----------------
__device__ __align__(16) float d_gxall[S_*B_*G_];
__device__ __align__(16) float d_hbuf[2][B_*U_];
__device__ __align__(16) float d_hdec[B_*U_];
__device__ __align__(16) float d_enc[B_*S_*U_];          // [b][s][u]
__device__ __align__(16) float d_pre[B_*S_*U_];          // rows b*64+s
__device__ __align__(16) float d_q[B_*U_];
__device__ __align__(16) float d_gpart[8][B_*G_];
__device__ __align__(16) float d_xcat[B_*U_];            // ctx only now
__device__ __align__(16) float d_demb[512*G_];           // Ed@dWx[1024:1280], rows t*32+b
__device__ __align__(16) float d_Hall[T_*B_*U_];         // rows t*32+b
__device__ __align__(16) float d_logits_alt[T_*B_*V_];
__device__ __align__(16) float d_WhP[U_*G_];
__device__ __align__(16) float d_dWxP[(U_+E_)*G_];
__device__ __align__(16) __nv_bfloat16 d_WfT3[(size_t)3*1024*VP_];
__device__ __align__(16) __nv_bfloat16 d_W1T3[3*1024*1024];
__device__ __align__(16) __nv_bfloat16 d_eWxT3[3*256*G_];
__device__ __align__(16) __nv_bfloat16 d_xembS[2048*768];
__device__ __align__(16) __nv_bfloat16 d_encS[(size_t)2048*3072];   // rows b*64+s
__device__ __align__(16) __nv_bfloat16 d_HallS[512*3072];           // rows t*32+b
__device__ unsigned int d_ctr[3*64];

__device__ __forceinline__ float sigm(float x) { return 1.f / (1.f + expf(-x)); }

// ---------------- setup kernels ----------------
__global__ void perm3(const float* __restrict__ W, float* __restrict__ out) {
    int idx = blockIdx.x * 256 + threadIdx.x;
    int k = idx / G_, c = idx - k * G_;
    int u = c / 3, g = c - u * 3;
    out[idx] = W[(size_t)k * G_ + g * U_ + u];
}

__global__ void embed_split(const int* __restrict__ enc_in, const float* __restrict__ Ee) {
    int idx = blockIdx.x * 256 + threadIdx.x;
    int r = idx >> 8, e = idx & 255;
    int s = r >> 5, b = r & 31;
    float x = Ee[(size_t)enc_in[b * S_ + s] * E_ + e];
    __nv_bfloat16 hi = __float2bfloat16(x);
    __nv_bfloat16 lo = __float2bfloat16(x - __bfloat162float(hi));
    size_t base = (size_t)r * 768;
    d_xembS[base + e] = hi; d_xembS[base + 256 + e] = lo; d_xembS[base + 512 + e] = hi;
}

// A [M][1024] fp32 -> [M][3072] bf16 = [hi|lo|hi]
__global__ void conv_splitA(const float* __restrict__ A, __nv_bfloat16* __restrict__ out) {
    int idx = blockIdx.x * 256 + threadIdx.x;
    int m = idx >> 10, k = idx & 1023;
    float x = A[idx];
    __nv_bfloat16 hi = __float2bfloat16(x);
    __nv_bfloat16 lo = __float2bfloat16(x - __bfloat162float(hi));
    size_t base = (size_t)m * 3072;
    out[base + k] = hi; out[base + 1024 + k] = lo; out[base + 2048 + k] = hi;
}

__global__ void conv_splitB_v8(const float* __restrict__ W, __nv_bfloat16* __restrict__ out,
                               int K, int N, int NP) {
    int idx = blockIdx.x * 256 + threadIdx.x;
    int per = NP >> 3;
    int k = idx / per, n = (idx - k * per) * 8;
    if (k >= K) return;
    float v[8];
    if (n + 8 <= N) {
        float4 a = *(const float4*)&W[(size_t)k * N + n];
        float4 b = *(const float4*)&W[(size_t)k * N + n + 4];
        v[0]=a.x; v[1]=a.y; v[2]=a.z; v[3]=a.w; v[4]=b.x; v[5]=b.y; v[6]=b.z; v[7]=b.w;
    } else {
#pragma unroll
        for (int j = 0; j < 8; j++) v[j] = (n + j < N) ? W[(size_t)k * N + n + j] : 0.f;
    }
    __nv_bfloat16 hi[8], lo[8];
#pragma unroll
    for (int j = 0; j < 8; j++) {
        hi[j] = __float2bfloat16(v[j]);
        lo[j] = __float2bfloat16(v[j] - __bfloat162float(hi[j]));
    }
    size_t p = (size_t)k * NP + n, sK = (size_t)K * NP;
    *(uint4*)&out[p]          = *(uint4*)hi;
    *(uint4*)&out[sK + p]     = *(uint4*)hi;
    *(uint4*)&out[2 * sK + p] = *(uint4*)lo;
}

// demb[t*32+b][c] = Ed[teacher[b][t]] @ dWxP[1024:1280][c]   (fp32, M=512, N=3072, K=256)
__global__ __launch_bounds__(128) void demb_gemm(
    const float* __restrict__ Ed, const int* __restrict__ teacher,
    const float* __restrict__ dWxP, float* __restrict__ demb)
{
    __shared__ float As[16][32];
    __shared__ float Bs[16][64];
    const int tid = threadIdx.x;
    const int tx = tid & 15, ty = tid >> 4;
    const int n0 = blockIdx.x * 64;
    const int m0 = blockIdx.y * 32;
    float acc[4][4] = {};
    for (int kt = 0; kt < 16; kt++) {
#pragma unroll
        for (int ii = tid; ii < 512; ii += 128) {
            int k = ii & 15, m = ii >> 4;
            int gr = m0 + m, t = gr >> 5, b = gr & 31;
            As[k][m] = Ed[(size_t)teacher[b * T_ + t] * E_ + kt * 16 + k];
        }
#pragma unroll
        for (int ii = tid; ii < 1024; ii += 128) {
            int k = ii >> 6, n = ii & 63;
            Bs[k][n] = dWxP[(size_t)(1024 + kt * 16 + k) * G_ + n0 + n];
        }
        __syncthreads();
#pragma unroll
        for (int kk = 0; kk < 16; kk++) {
            float4 av = *(const float4*)&As[kk][ty * 4];
            float a[4] = {av.x, av.y, av.z, av.w};
#pragma unroll
            for (int j = 0; j < 4; j++) {
                float bv = Bs[kk][tx * 4 + j];
#pragma unroll
                for (int i = 0; i < 4; i++) acc[i][j] += a[i] * bv;
            }
        }
        __syncthreads();
    }
#pragma unroll
    for (int i = 0; i < 4; i++)
#pragma unroll
        for (int j = 0; j < 4; j++)
            demb[(size_t)(m0 + ty * 4 + i) * G_ + n0 + tx * 4 + j] = acc[i][j];
}

// ---------------- tensor-core bf16 GEMM ----------------
__device__ __forceinline__ void mma_bf16(float* c, const uint32_t* a, const uint32_t* b) {
    asm volatile("mma.sync.aligned.m16n8k16.row.col.f32.bf16.bf16.f32 "
        "{%0,%1,%2,%3},{%4,%5,%6,%7},{%8,%9},{%0,%1,%2,%3};"
        : "+f"(c[0]), "+f"(c[1]), "+f"(c[2]), "+f"(c[3])
        : "r"(a[0]), "r"(a[1]), "r"(a[2]), "r"(a[3]), "r"(b[0]), "r"(b[1]));
}
__device__ __forceinline__ void ldsm_x4(uint32_t* r, uint32_t addr) {
    asm volatile("ldmatrix.sync.aligned.m8n8.x4.shared.b16 {%0,%1,%2,%3}, [%4];"
        : "=r"(r[0]), "=r"(r[1]), "=r"(r[2]), "=r"(r[3]) : "r"(addr));
}
__device__ __forceinline__ void ldsm_x2_trans(uint32_t* r, uint32_t addr) {
    asm volatile("ldmatrix.sync.aligned.m8n8.x2.trans.shared.b16 {%0,%1}, [%2];"
        : "=r"(r[0]), "=r"(r[1]) : "r"(addr));
}

// MODE 0: C[gm*ldC+gc]; MODE 1: logits scatter, global row = mofs+gm = t*32+b -> row b*16+t
template<int MODE>
__global__ __launch_bounds__(256) void gemm_bf16(
    const __nv_bfloat16* __restrict__ A, const __nv_bfloat16* __restrict__ Bkm,
    const float* __restrict__ bias, float* __restrict__ C,
    int ldC, int Nreal, int K3, int ldB, int mofs)
{
    __shared__ __nv_bfloat16 As[2][128 * 40];
    __shared__ __nv_bfloat16 Bs[2][32 * 72];
    const int tid = threadIdx.x;
    const int wid = tid >> 5, lane = tid & 31;
    const int gid = lane >> 2, tig = lane & 3;
    const int wm = wid & 3, wn = wid >> 2;
    const int m0 = blockIdx.y * 128, n0 = blockIdx.x * 64;

    const uint32_t asBase = (uint32_t)__cvta_generic_to_shared(&As[0][0]);
    const uint32_t bsBase = (uint32_t)__cvta_generic_to_shared(&Bs[0][0]);
    const int lquad = lane >> 3, l7 = lane & 7, l15 = lane & 15;
    const uint32_t aLane = (uint32_t)((((lquad & 1) * 8 + l7) * 80) + (lquad >> 1) * 16);

    float acc[2][4][4] = {};
    const int nkt = K3 >> 5;

    auto ldglobal = [&](int kt, int buf) {
#pragma unroll
        for (int i = 0; i < 2; i++) {
            int u4 = tid + i * 256;
            int row = u4 >> 2, c4 = u4 & 3;
            *(uint4*)&As[buf][row * 40 + c4 * 8] =
                *(const uint4*)&A[(size_t)(m0 + row) * K3 + kt * 32 + c4 * 8];
        }
        {
            int r = tid >> 3, c8 = tid & 7;
            *(uint4*)&Bs[buf][r * 72 + c8 * 8] =
                *(const uint4*)&Bkm[(size_t)(kt * 32 + r) * ldB + n0 + c8 * 8];
        }
    };

    ldglobal(0, 0);
    __syncthreads();
    for (int kt = 0; kt < nkt; kt++) {
        const int buf = kt & 1;
        if (kt + 1 < nkt) ldglobal(kt + 1, buf ^ 1);
#pragma unroll
        for (int ks = 0; ks < 2; ks++) {
            uint32_t a[2][4], b[4][2];
#pragma unroll
            for (int mi = 0; mi < 2; mi++)
                ldsm_x4(a[mi], asBase + (uint32_t)(buf * 128 * 80) +
                               (uint32_t)((wm * 32 + mi * 16) * 80 + ks * 32) + aLane);
#pragma unroll
            for (int ni = 0; ni < 4; ni++)
                ldsm_x2_trans(b[ni], bsBase + (uint32_t)(buf * 32 * 144) +
                              (uint32_t)(((ks * 16 + l15) * 72 + (wn * 32 + ni * 8)) * 2));
#pragma unroll
            for (int mi = 0; mi < 2; mi++)
#pragma unroll
                for (int ni = 0; ni < 4; ni++)
                    mma_bf16(acc[mi][ni], a[mi], b[ni]);
        }
        __syncthreads();
    }

#pragma unroll
    for (int mi = 0; mi < 2; mi++)
#pragma unroll
        for (int ni = 0; ni < 4; ni++) {
            int gm0 = m0 + wm * 32 + mi * 16 + gid;
            int gc0 = n0 + wn * 32 + ni * 8 + tig * 2;
#pragma unroll
            for (int e = 0; e < 4; e++) {
                int gm = gm0 + (e >> 1) * 8;
                int gc = gc0 + (e & 1);
                float v = acc[mi][ni][e];
                if (MODE == 1) {
                    if (gc < Nreal) {
                        int gg = mofs + gm;
                        int bb = gg & 31, tt = gg >> 5;
                        C[(size_t)(bb * T_ + tt) * Nreal + gc] = v + bias[gc];
                    }
                } else {
                    C[(size_t)gm * ldC + gc] = v + bias[gc];
                }
            }
        }
}

// ---------------- fused recurrence step (double-buffered register prefetch) --------
// GATE 0: q = h@W2 + b2   GATE 1: encoder GRU   GATE 2: decoder GRU (h0=0, demb via hin)
template<int BN, int TN, int NKC, int GATE>
__global__ __launch_bounds__(128) void step_gemm(
    const float* __restrict__ A, const float* __restrict__ Bm,
    const float* __restrict__ xb, const float* __restrict__ hb,
    const float* __restrict__ hin, float* __restrict__ hout,
    float* __restrict__ extra, float* __restrict__ part,
    float* __restrict__ qout, unsigned int* __restrict__ ctr,
    int N, int K)
{
    constexpr int PB = (16 * BN) / 128;
    __shared__ float As[16][32];
    __shared__ float Bs[16][BN];
    __shared__ int doneflag;
    const int tid = threadIdx.x;
    const int tx = tid & 15, ty = tid >> 4;
    const int n0 = blockIdx.x * BN;
    const int z = blockIdx.z;
    const int k0 = z * NKC * 16;

    float pa[4], pb[PB];
    auto ldA = [&](int kt) {
#pragma unroll
        for (int i = 0; i < 4; i++) {
            int ii = tid + i * 128, k = ii & 15, m = ii >> 4;
            pa[i] = A[(size_t)m * K + k0 + kt * 16 + k];
        }
    };
    auto ldB = [&](int kt) {
#pragma unroll
        for (int i = 0; i < PB; i++) {
            int ii = tid + i * 128, k = ii / BN, n = ii - k * BN;
            pb[i] = Bm[(size_t)(k0 + kt * 16 + k) * N + n0 + n];
        }
    };

    float acc[4][TN];
#pragma unroll
    for (int i = 0; i < 4; i++)
#pragma unroll
        for (int j = 0; j < TN; j++) acc[i][j] = 0.f;

    ldA(0); ldB(0);
    for (int kt = 0; kt < NKC; kt++) {
#pragma unroll
        for (int i = 0; i < 4; i++) {
            int ii = tid + i * 128;
            As[ii & 15][ii >> 4] = pa[i];
        }
#pragma unroll
        for (int i = 0; i < PB; i++) {
            int ii = tid + i * 128, k = ii / BN;
            Bs[k][ii - k * BN] = pb[i];
        }
        __syncthreads();
        if (kt + 1 < NKC) { ldA(kt + 1); ldB(kt + 1); }
#pragma unroll
        for (int kk = 0; kk < 16; kk++) {
            float4 av = *reinterpret_cast<const float4*>(&As[kk][ty * 4]);
            float a[4] = {av.x, av.y, av.z, av.w};
#pragma unroll
            for (int j = 0; j < TN; j++) {
                float bv = Bs[kk][tx * TN + j];
#pragma unroll
                for (int i = 0; i < 4; i++) acc[i][j] += a[i] * bv;
            }
        }
        __syncthreads();
    }
#pragma unroll
    for (int i = 0; i < 4; i++) {
        int gm = ty * 4 + i;
#pragma unroll
        for (int j = 0; j < TN; j++)
            part[((size_t)(z * 32 + gm)) * N + n0 + tx * TN + j] = acc[i][j];
    }
    __threadfence();
    __syncthreads();
    if (tid == 0) {
        unsigned int prev = atomicAdd(&ctr[blockIdx.x], 1u);
        doneflag = (prev == 7u);
        if (prev == 7u) ctr[blockIdx.x] = 0u;
    }
    __syncthreads();
    if (!doneflag) return;
    __threadfence();

    if (GATE == 0) {
#pragma unroll
        for (int i = 0; i < 16; i++) {
            int idx = tid + i * 128;
            int b = idx & 31, nl = idx >> 5;
            int n = n0 + nl;
            float s = 0.f;
#pragma unroll
            for (int zz = 0; zz < 8; zz++) s += part[((size_t)(zz * 32 + b)) * N + n];
            qout[b * U_ + n] = s + hb[n];
        }
    } else {
        const int u0 = n0 / 3;
#pragma unroll
        for (int i = 0; i < 4; i++) {
            int idx = tid + i * 128;
            int b = idx & 31, ul = idx >> 5;
            int u = u0 + ul;
            float g[3];
#pragma unroll
            for (int gg = 0; gg < 3; gg++) {
                float s = 0.f;
#pragma unroll
                for (int zz = 0; zz < 8; zz++)
                    s += part[((size_t)(zz * 32 + b)) * N + n0 + ul * 3 + gg];
                g[gg] = s;
            }
            float h;
            if (GATE == 1) {
                const float* gx = xb + (size_t)b * G_;
                float zg = sigm(gx[u] + g[0] + hb[u]);
                float rg = sigm(gx[U_ + u] + g[1] + hb[U_ + u]);
                float cg = tanhf(gx[2 * U_ + u] + rg * (g[2] + hb[2 * U_ + u]));
                h = zg * hin[b * U_ + u] + (1.f - zg) * cg;
                hout[b * U_ + u] = h;
                extra[(size_t)b * (S_ * U_) + u] = h;       // d_enc + s*U_
            } else {
                const float* de = hin + (size_t)b * G_ + n0 + ul * 3;   // demb row
                float zg = sigm(g[0] + de[0] + xb[u] + hb[u]);
                float rg = sigm(g[1] + de[1] + xb[U_ + u] + hb[U_ + u]);
                float cg = tanhf(g[2] + de[2] + xb[2 * U_ + u] + rg * hb[2 * U_ + u]);
                h = (1.f - zg) * cg;
                hout[b * U_ + u] = h;                        // d_hdec
                extra[(size_t)b * U_ + u] = h;               // d_Hall + t*B*U
            }
        }
    }
}

// ---------------- attention + context (512 threads, warp softmax, ctx only) --------
__global__ void attn_ctx(const float* __restrict__ Va, const float* __restrict__ bvp)
{
    const int b = blockIdx.x, tid = threadIdx.x;
    __shared__ float qs[U_];
    __shared__ float sc[S_];

    for (int u = tid; u < U_; u += 512) qs[u] = d_q[b * U_ + u];
    __syncthreads();

    const int w = tid >> 5, lane = tid & 31;
    for (int s = w; s < S_; s += 16) {
        const float* pr = d_pre + (size_t)b * (S_ * U_) + (size_t)s * U_;
        float p = 0.f;
        for (int u = lane; u < U_; u += 32) p += tanhf(pr[u] + qs[u]) * Va[u];
#pragma unroll
        for (int o = 16; o > 0; o >>= 1) p += __shfl_xor_sync(0xffffffffu, p, o);
        if (lane == 0) sc[s] = p + bvp[0];
    }
    __syncthreads();

    if (tid < 32) {
        float v0 = sc[tid], v1 = sc[tid + 32];
        float m = fmaxf(v0, v1);
#pragma unroll
        for (int o = 16; o > 0; o >>= 1) m = fmaxf(m, __shfl_xor_sync(0xffffffffu, m, o));
        float e0 = expf(v0 - m), e1 = expf(v1 - m);
        float s = e0 + e1;
#pragma unroll
        for (int o = 16; o > 0; o >>= 1) s += __shfl_xor_sync(0xffffffffu, s, o);
        float inv = 1.f / s;
        sc[tid] = e0 * inv; sc[tid + 32] = e1 * inv;
    }
    __syncthreads();

    for (int u = tid; u < U_; u += 512) {
        float a = 0.f;
        const float* eb = d_enc + (size_t)b * (S_ * U_) + u;
#pragma unroll 8
        for (int s = 0; s < S_; s++) a += sc[s] * eb[(size_t)s * U_];
        d_xcat[(size_t)b * U_ + u] = a;
    }
}

// ---------------- argmax ----------------
__global__ void argmax_k(const float* __restrict__ logits, long long* outI, float* outF, int asFloat)
{
    const int row = blockIdx.x;
    const float* p = logits + (size_t)row * V_;
    const int tid = threadIdx.x;
    float best = -INFINITY; int bi = 0;
    for (int v = tid; v < V_; v += 256) {
        float val = p[v];
        if (val > best) { best = val; bi = v; }
    }
    __shared__ float bvs[256]; __shared__ int bis[256];
    bvs[tid] = best; bis[tid] = bi;
    __syncthreads();
    for (int st = 128; st > 0; st >>= 1) {
        if (tid < st) {
            float ov = bvs[tid + st]; int oi = bis[tid + st];
            if (ov > bvs[tid] || (ov == bvs[tid] && oi < bis[tid])) { bvs[tid] = ov; bis[tid] = oi; }
        }
        __syncthreads();
    }
    if (tid == 0) {
        if (asFloat) outF[row] = (float)bis[0];
        else         outI[row] = (long long)bis[0];
    }
}

// ---------------- launcher ----------------
static float* symaddr(const void* sym) {
    void* p = nullptr;
    cudaGetSymbolAddress(&p, sym);
    return (float*)p;
}

extern "C" void kernel_launch(void* const* d_in, const int* in_sizes, int n_in,
                              void* d_out, int out_size)
{
    static cudaStream_t s2 = nullptr;
    static cudaEvent_t ev[16];
    if (!s2) {
        cudaStreamCreateWithFlags(&s2, cudaStreamNonBlocking);
        for (int i = 0; i < 16; i++) cudaEventCreateWithFlags(&ev[i], cudaEventDisableTiming);
    }

    const int s0 = (n_in >= 22) ? 4 : 2;
    const int*   enc_in  = (const int*)d_in[0];
    const int*   teacher = (const int*)d_in[1];
    const float* Ee      = (const float*)d_in[s0 + 0];
    const float* eWx     = (const float*)d_in[s0 + 1];
    const float* eWh     = (const float*)d_in[s0 + 2];
    const float* eb_in   = (const float*)d_in[s0 + 3];
    const float* eb_rec  = (const float*)d_in[s0 + 4];
    const float* Ed      = (const float*)d_in[s0 + 5];
    const float* dWx     = (const float*)d_in[s0 + 6];
    const float* db_in   = (const float*)d_in[s0 + 8];
    const float* db_rec  = (const float*)d_in[s0 + 9];
    const float* W1      = (const float*)d_in[s0 + 10];
    const float* b1      = (const float*)d_in[s0 + 11];
    const float* W2      = (const float*)d_in[s0 + 12];
    const float* b2      = (const float*)d_in[s0 + 13];
    const float* Va      = (const float*)d_in[s0 + 14];
    const float* bvp     = (const float*)d_in[s0 + 15];
    const float* Wf      = (const float*)d_in[s0 + 16];
    const float* bf      = (const float*)d_in[s0 + 17];

    float* hbase = symaddr(d_hbuf);
    float* hdec  = symaddr(d_hdec);
    float* encp  = symaddr(d_enc);
    float* prep  = symaddr(d_pre);
    float* qp    = symaddr(d_q);
    float* gpart = symaddr(d_gpart);
    float* xcat  = symaddr(d_xcat);
    float* demb  = symaddr(d_demb);
    float* Hall  = symaddr(d_Hall);
    float* lalt  = symaddr(d_logits_alt);
    float* gxall = symaddr(d_gxall);
    float* WhP   = symaddr(d_WhP);
    float* dWxP  = symaddr(d_dWxP);
    unsigned int* ctr; { void* p; cudaGetSymbolAddress(&p, d_ctr); ctr = (unsigned int*)p; }
    __nv_bfloat16* WfT3;  { void* p; cudaGetSymbolAddress(&p, d_WfT3);  WfT3  = (__nv_bfloat16*)p; }
    __nv_bfloat16* W1T3;  { void* p; cudaGetSymbolAddress(&p, d_W1T3);  W1T3  = (__nv_bfloat16*)p; }
    __nv_bfloat16* eWxT3; { void* p; cudaGetSymbolAddress(&p, d_eWxT3); eWxT3 = (__nv_bfloat16*)p; }
    __nv_bfloat16* xembS; { void* p; cudaGetSymbolAddress(&p, d_xembS); xembS = (__nv_bfloat16*)p; }
    __nv_bfloat16* encS;  { void* p; cudaGetSymbolAddress(&p, d_encS);  encS  = (__nv_bfloat16*)p; }
    __nv_bfloat16* HallS; { void* p; cudaGetSymbolAddress(&p, d_HallS); HallS = (__nv_bfloat16*)p; }

    const long long LOGN = (long long)B_ * T_ * V_;
    float* logits_dst = (float*)d_out;
    long long* predI = nullptr; float* predF = nullptr; int asFloat = 0;
    if ((long long)out_size == LOGN + 512) { predF = (float*)d_out + LOGN; asFloat = 1; }
    else if ((long long)out_size == LOGN + 1024) { predI = (long long*)((float*)d_out + LOGN); }
    else if (out_size == 512) { logits_dst = lalt; predI = (long long*)d_out; }

    cudaMemsetAsync(hbase, 0, (size_t)B_ * U_ * sizeof(float));

    // main stream front (kernels 1..4): eWh perm, eWx split, embed, gx chunk0 (steps 0-15)
    perm3<<<U_ * G_ / 256, 256>>>(eWh, WhP);
    conv_splitB_v8<<<(E_ * (G_ / 8) + 255) / 256, 256>>>(eWx, eWxT3, E_, G_, G_);
    embed_split<<<2048, 256>>>(enc_in, Ee);
    gemm_bf16<0><<<dim3(G_ / 64, 4), 256>>>(xembS, eWxT3, eb_in, gxall, G_, G_, 768, G_, 0);

    // encoder steps 0 and 1 (kernels 5,6 -> ncu -s 5 captures a step_gemm)
    for (int s = 0; s < 2; s++) {
        float* hin  = hbase + (size_t)(s & 1) * B_ * U_;
        float* hout = hbase + (size_t)((s + 1) & 1) * B_ * U_;
        step_gemm<48,3,8,1><<<dim3(G_ / 48, 1, 8), 128>>>(
            hin, WhP, gxall + (size_t)s * B_ * G_, eb_rec,
            hin, hout, encp + (size_t)s * U_, gpart, nullptr, ctr, G_, U_);
    }

    // fork side stream: gx chunks 1-3, W1 split, dWx perm, demb, Wf split
    cudaEventRecord(ev[0], 0);
    cudaStreamWaitEvent(s2, ev[0], 0);
    for (int c = 1; c < 4; c++) {
        gemm_bf16<0><<<dim3(G_ / 64, 4), 256, 0, s2>>>(
            xembS + (size_t)c * 512 * 768, eWxT3, eb_in,
            gxall + (size_t)c * 512 * G_, G_, G_, 768, G_, 0);
        cudaEventRecord(ev[c], s2);                 // gx chunk c ready
    }
    conv_splitB_v8<<<(U_ * (U_ / 8) + 255) / 256, 256, 0, s2>>>(W1, W1T3, U_, U_, U_);
    cudaEventRecord(ev[4], s2);                     // W1T3 ready
    perm3<<<(U_ + E_) * G_ / 256, 256, 0, s2>>>(dWx, dWxP);
    demb_gemm<<<dim3(G_ / 64, 16), 128, 0, s2>>>(Ed, teacher, dWxP, demb);
    cudaEventRecord(ev[5], s2);                     // dWxP + demb ready
    conv_splitB_v8<<<(U_ * (VP_ / 8) + 255) / 256, 256, 0, s2>>>(Wf, WfT3, U_, V_, VP_);

    // encoder steps 2..63 (wait for gx chunk c before step 16c)
    for (int s = 2; s < S_; s++) {
        if ((s & 15) == 0) cudaStreamWaitEvent(0, ev[s >> 4], 0);
        float* hin  = hbase + (size_t)(s & 1) * B_ * U_;
        float* hout = hbase + (size_t)((s + 1) & 1) * B_ * U_;
        step_gemm<48,3,8,1><<<dim3(G_ / 48, 1, 8), 128>>>(
            hin, WhP, gxall + (size_t)s * B_ * G_, eb_rec,
            hin, hout, encp + (size_t)s * U_, gpart, nullptr, ctr, G_, U_);
    }

    // pre_enc: bulk split of d_enc then GEMM (needs W1T3)
    conv_splitA<<<(B_ * S_ * U_) / 256, 256>>>(encp, encS);
    cudaStreamWaitEvent(0, ev[4], 0);
    gemm_bf16<0><<<dim3(U_ / 64, (B_ * S_) / 128), 256>>>(encS, W1T3, b1, prep, U_, U_, 3072, U_, 0);

    // decoder (needs dWxP + demb)
    cudaStreamWaitEvent(0, ev[5], 0);
    for (int t = 0; t < T_; t++) {
        const float* hd = (t == 0) ? hbase : hdec;
        step_gemm<64,4,8,0><<<dim3(U_ / 64, 1, 8), 128>>>(
            hd, W2, nullptr, b2, nullptr, nullptr, nullptr, gpart, qp, ctr + 64, U_, U_);
        attn_ctx<<<B_, 512>>>(Va, bvp);
        step_gemm<48,3,8,2><<<dim3(G_ / 48, 1, 8), 128>>>(
            xcat, dWxP, db_in, db_rec, demb + (size_t)t * 32 * G_, hdec,
            Hall + (size_t)t * B_ * U_, gpart, nullptr, ctr + 128, G_, U_);
        if ((t & 3) == 3) {
            int c = t >> 2;
            cudaEventRecord(ev[7 + c], 0);
            cudaStreamWaitEvent(s2, ev[7 + c], 0);
            conv_splitA<<<512, 256, 0, s2>>>(Hall + (size_t)c * 128 * U_,
                                             HallS + (size_t)c * 128 * 3072);
            gemm_bf16<1><<<dim3(VP_ / 64, 1), 256, 0, s2>>>(
                HallS + (size_t)c * 128 * 3072, WfT3, bf, logits_dst, 0, V_, 3072, VP_, c * 128);
        }
    }

    // join side stream, then argmax
    cudaEventRecord(ev[11], s2);
    cudaStreamWaitEvent(0, ev[11], 0);
    if (predI || predF) argmax_k<<<T_ * B_, 256>>>(logits_dst, predI, predF, asFloat);
}